// round 4
// baseline (speedup 1.0000x reference)
#include <cuda_runtime.h>
#include <cstdint>

#define ST 512
#define SI 2048
#define SS 2560
#define DM 3072
#define NH 24
#define HD 128
#define E3 9216
#define ATTN_SCALE 0.08838834764831845f  // 1/sqrt(128)

// ---------------- scratch (device globals: no allocations allowed) ----------
__device__ float g_QKV[(size_t)SS * E3];      // [s][9216]  (text rows 0..511, image 512..2559)
__device__ float g_Q[(size_t)NH * SS * HD];   // [h][s][d]
__device__ float g_K[(size_t)NH * SS * HD];
__device__ float g_V[(size_t)NH * SS * HD];
__device__ float g_O[(size_t)SS * NH * HD];   // [s][h*128+d]

// ---------------------------------------------------------------------------
// Generic C[M,N] = A[M,K] * B[N,K]^T + bias[N]
// 128x128 tile, BK=16, 256 threads, 8x8 micro-tile.
// Smem k-major with XOR-4 swizzle: element (k,row) stored at [k][row ^ 4*(k&7)].
// ---------------------------------------------------------------------------
__global__ void __launch_bounds__(256, 2) gemm_bias(
    const float* __restrict__ A, const float* __restrict__ B,
    const float* __restrict__ bias, float* __restrict__ C,
    int K, int N)
{
    __shared__ float As[16][128];
    __shared__ float Bs[16][128];

    const int tid = threadIdx.x;
    const int tx = tid & 15;
    const int ty = tid >> 4;
    const int lk = tid & 15;          // k index for loading
    const int lr = tid >> 4;          // row base for loading
    const int rowBase = blockIdx.y * 128;
    const int colBase = blockIdx.x * 128;
    const int smsk = (lk & 7) * 4;

    float acc[8][8];
#pragma unroll
    for (int i = 0; i < 8; i++)
#pragma unroll
        for (int j = 0; j < 8; j++) acc[i][j] = 0.f;

    const float* Ap = A + (size_t)rowBase * K + lk;
    const float* Bp = B + (size_t)colBase * K + lk;

    for (int kt = 0; kt < K; kt += 16) {
#pragma unroll
        for (int rr = 0; rr < 128; rr += 16)
            As[lk][(lr + rr) ^ smsk] = Ap[(size_t)(lr + rr) * K + kt];
#pragma unroll
        for (int rr = 0; rr < 128; rr += 16)
            Bs[lk][(lr + rr) ^ smsk] = Bp[(size_t)(lr + rr) * K + kt];
        __syncthreads();

#pragma unroll
        for (int kk = 0; kk < 16; kk++) {
            const int sw = (kk & 7) * 4;
            float4 a0 = *(const float4*)&As[kk][(ty * 8) ^ sw];
            float4 a1 = *(const float4*)&As[kk][(ty * 8 + 4) ^ sw];
            float4 b0 = *(const float4*)&Bs[kk][(tx * 4) ^ sw];
            float4 b1 = *(const float4*)&Bs[kk][(64 + tx * 4) ^ sw];
            float a[8] = {a0.x, a0.y, a0.z, a0.w, a1.x, a1.y, a1.z, a1.w};
            float b[8] = {b0.x, b0.y, b0.z, b0.w, b1.x, b1.y, b1.z, b1.w};
#pragma unroll
            for (int i = 0; i < 8; i++)
#pragma unroll
                for (int j = 0; j < 8; j++)
                    acc[i][j] = fmaf(a[i], b[j], acc[i][j]);
        }
        __syncthreads();
    }

    // epilogue: this thread owns cols {c0..c0+3} and {c0+64..c0+67}
    const int c0 = colBase + tx * 4;
    float4 bi0 = *(const float4*)&bias[c0];
    float4 bi1 = *(const float4*)&bias[c0 + 64];
#pragma unroll
    for (int i = 0; i < 8; i++) {
        const size_t r = (size_t)(rowBase + ty * 8 + i);
        float4 o0 = make_float4(acc[i][0] + bi0.x, acc[i][1] + bi0.y,
                                acc[i][2] + bi0.z, acc[i][3] + bi0.w);
        float4 o1 = make_float4(acc[i][4] + bi1.x, acc[i][5] + bi1.y,
                                acc[i][6] + bi1.z, acc[i][7] + bi1.w);
        *(float4*)&C[r * N + c0] = o0;
        *(float4*)&C[r * N + c0 + 64] = o1;
    }
}

// ---------------------------------------------------------------------------
// Per-(s,h): RMS-norm q,k (text uses naq/nak, image nq/nk), RoPE q,k,
// scatter q,k,v into [h][s][d] layout. 128 threads = one head-dim.
// ---------------------------------------------------------------------------
__global__ void rmsrope_kernel(const float* __restrict__ nq, const float* __restrict__ nk,
                               const float* __restrict__ naq, const float* __restrict__ nak,
                               const float* __restrict__ cosT, const float* __restrict__ sinT)
{
    const int s = blockIdx.x;
    const int h = blockIdx.y;
    const int d = threadIdx.x;

    const float* row = g_QKV + (size_t)s * E3;
    float q = row[h * HD + d];
    float k = row[DM + h * HD + d];
    float v = row[2 * DM + h * HD + d];

    float qq = q * q, kk = k * k;
#pragma unroll
    for (int off = 16; off; off >>= 1) {
        qq += __shfl_xor_sync(0xffffffffu, qq, off);
        kk += __shfl_xor_sync(0xffffffffu, kk, off);
    }
    __shared__ float wq[4], wk[4];
    const int wid = d >> 5, lane = d & 31;
    if (lane == 0) { wq[wid] = qq; wk[wid] = kk; }
    __syncthreads();
    const float sq = wq[0] + wq[1] + wq[2] + wq[3];
    const float sk = wk[0] + wk[1] + wk[2] + wk[3];
    const float rq = rsqrtf(sq * (1.f / 128.f) + 1e-6f);
    const float rk = rsqrtf(sk * (1.f / 128.f) + 1e-6f);

    const bool txt = (s < ST);
    const float qw = txt ? naq[d] : nq[d];
    const float kw = txt ? nak[d] : nk[d];

    __shared__ float qb[128], kb[128];
    qb[d] = q * rq * qw;
    kb[d] = k * rk * kw;

    const size_t base = ((size_t)h * SS + s) * HD;
    g_V[base + d] = v;
    __syncthreads();

    if (d < 64) {
        const float c = cosT[s * 64 + d];
        const float sn = sinT[s * 64 + d];
        float q1 = qb[2 * d], q2 = qb[2 * d + 1];
        g_Q[base + 2 * d]     = q1 * c - q2 * sn;
        g_Q[base + 2 * d + 1] = q2 * c + q1 * sn;
        float k1 = kb[2 * d], k2 = kb[2 * d + 1];
        g_K[base + 2 * d]     = k1 * c - k2 * sn;
        g_K[base + 2 * d + 1] = k2 * c + k1 * sn;
    }
}

// ---------------------------------------------------------------------------
// Flash attention: BQ=128 queries x full S, BKV=64 per step, 256 threads.
// smem: Qs[d][128] swz, Ks[d][64] swz, Vs[64][128], Ps[64][128] swz = 160 KB.
// Each thread: 8 rows (ty*8+i); score cols tx*4+j; O cols {tx*4+j, 64+tx*4+j}.
// ---------------------------------------------------------------------------
#define ATTN_SMEM ((128 * 128 + 128 * 64 + 64 * 128 + 64 * 128) * 4)

__global__ void __launch_bounds__(256, 1) attn_kernel()
{
    extern __shared__ float sm[];
    float* Qs = sm;                    // [128][128] element (d,r) at [d][r ^ 4*((d>>2)&7)]
    float* Ks = Qs + 128 * 128;        // [128][64]  same swizzle
    float* Vs = Ks + 128 * 64;         // [64][128]  row-major
    float* Ps = Vs + 64 * 128;         // [64][128]  element (j,r) at [j][r ^ 4*((j>>2)&7)]

    const int tid = threadIdx.x;
    const int tx = tid & 15;
    const int ty = tid >> 4;
    const int h = blockIdx.y;
    const int q0 = blockIdx.x * 128;

    const float* Qg = g_Q + ((size_t)h * SS + q0) * HD;
    const float* Kg = g_K + (size_t)h * SS * HD;
    const float* Vg = g_V + (size_t)h * SS * HD;

    // load Q tile (transposed + swizzled)
#pragma unroll
    for (int it = 0; it < 16; it++) {
        int idx = tid + it * 256;            // one float4 each
        int r = idx >> 5;
        int d4 = (idx & 31) * 4;
        float4 v = *(const float4*)&Qg[(size_t)r * HD + d4];
        int rs = r ^ (((d4 >> 2) & 7) * 4);
        Qs[(d4 + 0) * 128 + rs] = v.x;
        Qs[(d4 + 1) * 128 + rs] = v.y;
        Qs[(d4 + 2) * 128 + rs] = v.z;
        Qs[(d4 + 3) * 128 + rs] = v.w;
    }

    float m[8], l[8], acc[8][8];
#pragma unroll
    for (int i = 0; i < 8; i++) {
        m[i] = -1e30f; l[i] = 0.f;
#pragma unroll
        for (int j = 0; j < 8; j++) acc[i][j] = 0.f;
    }

    for (int kt = 0; kt < SS; kt += 64) {
        __syncthreads();   // protects Q load (first iter) and Ks/Vs/Ps reuse
        // K tile (transposed + swizzled), V tile (row-major)
#pragma unroll
        for (int it = 0; it < 8; it++) {
            int idx = tid + it * 256;
            int r = idx >> 5;
            int d4 = (idx & 31) * 4;
            float4 v = *(const float4*)&Kg[(size_t)(kt + r) * HD + d4];
            int rs = r ^ (((d4 >> 2) & 7) * 4);
            Ks[(d4 + 0) * 64 + rs] = v.x;
            Ks[(d4 + 1) * 64 + rs] = v.y;
            Ks[(d4 + 2) * 64 + rs] = v.z;
            Ks[(d4 + 3) * 64 + rs] = v.w;
        }
#pragma unroll
        for (int it = 0; it < 8; it++) {
            int idx = tid + it * 256;
            int r = idx >> 5;
            int d4 = (idx & 31) * 4;
            *(float4*)&Vs[r * 128 + d4] = *(const float4*)&Vg[(size_t)(kt + r) * HD + d4];
        }
        __syncthreads();

        // S = Q K^T (8x4 per thread)
        float sc[8][4];
#pragma unroll
        for (int i = 0; i < 8; i++)
#pragma unroll
            for (int j = 0; j < 4; j++) sc[i][j] = 0.f;

#pragma unroll 8
        for (int kk = 0; kk < 128; kk++) {
            const int sw = ((kk >> 2) & 7) * 4;
            float4 a0 = *(const float4*)&Qs[kk * 128 + ((ty * 8) ^ sw)];
            float4 a1 = *(const float4*)&Qs[kk * 128 + ((ty * 8 + 4) ^ sw)];
            float4 b0 = *(const float4*)&Ks[kk * 64 + ((tx * 4) ^ sw)];
            float a[8] = {a0.x, a0.y, a0.z, a0.w, a1.x, a1.y, a1.z, a1.w};
            float b[4] = {b0.x, b0.y, b0.z, b0.w};
#pragma unroll
            for (int i = 0; i < 8; i++)
#pragma unroll
                for (int j = 0; j < 4; j++)
                    sc[i][j] = fmaf(a[i], b[j], sc[i][j]);
        }

        // online softmax (row reductions over the 16 tx lanes)
        const int pmk = (tx & 7) * 4;
#pragma unroll
        for (int i = 0; i < 8; i++) {
#pragma unroll
            for (int j = 0; j < 4; j++) sc[i][j] *= ATTN_SCALE;
            float rmax = fmaxf(fmaxf(sc[i][0], sc[i][1]), fmaxf(sc[i][2], sc[i][3]));
#pragma unroll
            for (int off = 8; off; off >>= 1)
                rmax = fmaxf(rmax, __shfl_xor_sync(0xffffffffu, rmax, off));
            const float mn = fmaxf(m[i], rmax);
            const float f = __expf(m[i] - mn);
            m[i] = mn;
            float rs = 0.f;
#pragma unroll
            for (int j = 0; j < 4; j++) {
                sc[i][j] = __expf(sc[i][j] - mn);
                rs += sc[i][j];
            }
#pragma unroll
            for (int off = 8; off; off >>= 1)
                rs += __shfl_xor_sync(0xffffffffu, rs, off);
            l[i] = l[i] * f + rs;
#pragma unroll
            for (int jj = 0; jj < 8; jj++) acc[i][jj] *= f;
            // store P (swizzled): logical (jj=tx*4+j, r=ty*8+i)
#pragma unroll
            for (int j = 0; j < 4; j++)
                Ps[(tx * 4 + j) * 128 + ((ty * 8 + i) ^ pmk)] = sc[i][j];
        }
        __syncthreads();

        // O += P V
#pragma unroll 4
        for (int j = 0; j < 64; j++) {
            const int sw = ((j >> 2) & 7) * 4;
            float4 p0 = *(const float4*)&Ps[j * 128 + ((ty * 8) ^ sw)];
            float4 p1 = *(const float4*)&Ps[j * 128 + ((ty * 8 + 4) ^ sw)];
            float4 v0 = *(const float4*)&Vs[j * 128 + tx * 4];
            float4 v1 = *(const float4*)&Vs[j * 128 + 64 + tx * 4];
            float p[8] = {p0.x, p0.y, p0.z, p0.w, p1.x, p1.y, p1.z, p1.w};
#pragma unroll
            for (int i = 0; i < 8; i++) {
                acc[i][0] = fmaf(p[i], v0.x, acc[i][0]);
                acc[i][1] = fmaf(p[i], v0.y, acc[i][1]);
                acc[i][2] = fmaf(p[i], v0.z, acc[i][2]);
                acc[i][3] = fmaf(p[i], v0.w, acc[i][3]);
                acc[i][4] = fmaf(p[i], v1.x, acc[i][4]);
                acc[i][5] = fmaf(p[i], v1.y, acc[i][5]);
                acc[i][6] = fmaf(p[i], v1.z, acc[i][6]);
                acc[i][7] = fmaf(p[i], v1.w, acc[i][7]);
            }
        }
    }

    // epilogue: divide by l, write [s][h*128+d]
    const int c0 = tx * 4;
#pragma unroll
    for (int i = 0; i < 8; i++) {
        const float inv = 1.f / l[i];
        const size_t orow = (size_t)(q0 + ty * 8 + i) * (NH * HD) + h * HD;
        float4 o0 = make_float4(acc[i][0] * inv, acc[i][1] * inv,
                                acc[i][2] * inv, acc[i][3] * inv);
        float4 o1 = make_float4(acc[i][4] * inv, acc[i][5] * inv,
                                acc[i][6] * inv, acc[i][7] * inv);
        *(float4*)&g_O[orow + c0] = o0;
        *(float4*)&g_O[orow + c0 + 64] = o1;
    }
}

// ---------------------------------------------------------------------------
extern "C" void kernel_launch(void* const* d_in, const int* in_sizes, int n_in,
                              void* d_out, int out_size)
{
    (void)in_sizes; (void)n_in; (void)out_size;
    const float* hidden = (const float*)d_in[0];
    const float* enc    = (const float*)d_in[1];
    const float* cosT   = (const float*)d_in[2];
    const float* sinT   = (const float*)d_in[3];
    const float* w_qkv  = (const float*)d_in[4];
    const float* b_qkv  = (const float*)d_in[5];
    const float* w_add  = (const float*)d_in[6];
    const float* b_add  = (const float*)d_in[7];
    const float* nq_w   = (const float*)d_in[8];
    const float* nk_w   = (const float*)d_in[9];
    const float* naq_w  = (const float*)d_in[10];
    const float* nak_w  = (const float*)d_in[11];
    const float* w_out  = (const float*)d_in[12];
    const float* b_out  = (const float*)d_in[13];
    const float* w_ao   = (const float*)d_in[14];
    const float* b_ao   = (const float*)d_in[15];
    float* out = (float*)d_out;

    float *qkv = nullptr, *obuf = nullptr;
    cudaGetSymbolAddress((void**)&qkv, g_QKV);
    cudaGetSymbolAddress((void**)&obuf, g_O);
    cudaFuncSetAttribute(attn_kernel, cudaFuncAttributeMaxDynamicSharedMemorySize, ATTN_SMEM);

    // QKV projections (text rows 0..511 use w_add; image rows use w_qkv)
    gemm_bias<<<dim3(E3 / 128, ST / 128), 256>>>(enc, w_add, b_add, qkv, DM, E3);
    gemm_bias<<<dim3(E3 / 128, SI / 128), 256>>>(hidden, w_qkv, b_qkv,
                                                 qkv + (size_t)ST * E3, DM, E3);
    // RMS norm + RoPE + scatter to [h][s][d]
    rmsrope_kernel<<<dim3(SS, NH), 128>>>(nq_w, nk_w, naq_w, nak_w, cosT, sinT);
    // attention
    attn_kernel<<<dim3(SS / 128, NH), 256, ATTN_SMEM>>>();
    // output projections: img_out first, then txt_out
    gemm_bias<<<dim3(DM / 128, SI / 128), 256>>>(obuf + (size_t)ST * DM, w_out, b_out,
                                                 out, DM, DM);
    gemm_bias<<<dim3(DM / 128, ST / 128), 256>>>(obuf, w_ao, b_ao,
                                                 out + (size_t)SI * DM, DM, DM);
}

// round 5
// speedup vs baseline: 2.5837x; 2.5837x over previous
#include <cuda_runtime.h>
#include <cstdint>

#define ST 512
#define SI 2048
#define SS 2560
#define DM 3072
#define NH 24
#define HD 128
#define E3 9216
#define ATTN_SCALE 0.08838834764831845f  // 1/sqrt(128)

// ---------------- scratch (device globals: no allocations allowed) ----------
__device__ float g_QKV[(size_t)SS * E3];      // [s][9216]
__device__ float g_Q[(size_t)NH * SS * HD];   // [h][s][d]
__device__ float g_K[(size_t)NH * SS * HD];
__device__ float g_V[(size_t)NH * SS * HD];
__device__ float g_O[(size_t)SS * NH * HD];   // [s][h*128+d]

__device__ __forceinline__ float to_tf32(float x) {
    float r;
    asm("cvt.rna.tf32.f32 %0, %1;" : "=f"(r) : "f"(x));
    return r;
}

__device__ __forceinline__ void mma_tf32(float (&c)[4], const unsigned (&a)[4],
                                         const unsigned (&b)[2]) {
    asm volatile(
        "mma.sync.aligned.m16n8k8.row.col.f32.tf32.tf32.f32 "
        "{%0,%1,%2,%3}, {%4,%5,%6,%7}, {%8,%9}, {%0,%1,%2,%3};\n"
        : "+f"(c[0]), "+f"(c[1]), "+f"(c[2]), "+f"(c[3])
        : "r"(a[0]), "r"(a[1]), "r"(a[2]), "r"(a[3]), "r"(b[0]), "r"(b[1]));
}

// ---------------------------------------------------------------------------
// C[M,N] = A[M,K] * B[N,K]^T + bias[N], tf32 tensor cores.
// 128x128 tile, BK=16, 256 threads = 8 warps (2x4), warp tile 64x32.
// Smem stride 20 floats -> conflict-free m16n8k8 fragment reads.
// ---------------------------------------------------------------------------
__global__ void __launch_bounds__(256, 2) gemm_tf32(
    const float* __restrict__ A, const float* __restrict__ B,
    const float* __restrict__ bias, float* __restrict__ C,
    int K, int N)
{
    __shared__ float As[128 * 20];
    __shared__ float Bs[128 * 20];

    const int tid  = threadIdx.x;
    const int lane = tid & 31;
    const int wid  = tid >> 5;
    const int wm   = wid >> 2;   // 0..1
    const int wn   = wid & 3;    // 0..3
    const int rl   = lane >> 2;  // 0..7
    const int cq   = lane & 3;   // 0..3
    const int rowBase = blockIdx.y * 128;
    const int colBase = blockIdx.x * 128;

    const int lr = tid >> 1;          // 0..127
    const int lk = (tid & 1) * 8;     // 0 or 8

    float acc[4][4][4];
#pragma unroll
    for (int mt = 0; mt < 4; mt++)
#pragma unroll
        for (int nt = 0; nt < 4; nt++)
#pragma unroll
            for (int e = 0; e < 4; e++) acc[mt][nt][e] = 0.f;

    const float* Ap = A + (size_t)(rowBase + lr) * K + lk;
    const float* Bp = B + (size_t)(colBase + lr) * K + lk;

    for (int kt = 0; kt < K; kt += 16) {
        float4 av = *(const float4*)(Ap + kt);
        float4 av2 = *(const float4*)(Ap + kt + 4);
        float4 bv = *(const float4*)(Bp + kt);
        float4 bv2 = *(const float4*)(Bp + kt + 4);
        __syncthreads();
        {
            float4 t;
            t.x = to_tf32(av.x);  t.y = to_tf32(av.y);
            t.z = to_tf32(av.z);  t.w = to_tf32(av.w);
            *(float4*)&As[lr * 20 + lk] = t;
            t.x = to_tf32(av2.x); t.y = to_tf32(av2.y);
            t.z = to_tf32(av2.z); t.w = to_tf32(av2.w);
            *(float4*)&As[lr * 20 + lk + 4] = t;
            t.x = to_tf32(bv.x);  t.y = to_tf32(bv.y);
            t.z = to_tf32(bv.z);  t.w = to_tf32(bv.w);
            *(float4*)&Bs[lr * 20 + lk] = t;
            t.x = to_tf32(bv2.x); t.y = to_tf32(bv2.y);
            t.z = to_tf32(bv2.z); t.w = to_tf32(bv2.w);
            *(float4*)&Bs[lr * 20 + lk + 4] = t;
        }
        __syncthreads();

#pragma unroll
        for (int kk = 0; kk < 16; kk += 8) {
            unsigned af[4][4];
#pragma unroll
            for (int mt = 0; mt < 4; mt++) {
                const float* ap = &As[(wm * 64 + mt * 16 + rl) * 20 + kk + cq];
                af[mt][0] = __float_as_uint(ap[0]);
                af[mt][1] = __float_as_uint(ap[8 * 20]);
                af[mt][2] = __float_as_uint(ap[4]);
                af[mt][3] = __float_as_uint(ap[8 * 20 + 4]);
            }
            unsigned bf[4][2];
#pragma unroll
            for (int nt = 0; nt < 4; nt++) {
                const float* bp = &Bs[(wn * 32 + nt * 8 + rl) * 20 + kk + cq];
                bf[nt][0] = __float_as_uint(bp[0]);
                bf[nt][1] = __float_as_uint(bp[4]);
            }
#pragma unroll
            for (int mt = 0; mt < 4; mt++)
#pragma unroll
                for (int nt = 0; nt < 4; nt++)
                    mma_tf32(acc[mt][nt], af[mt], bf[nt]);
        }
    }

    // epilogue
#pragma unroll
    for (int mt = 0; mt < 4; mt++) {
        const int r0 = rowBase + wm * 64 + mt * 16 + rl;
#pragma unroll
        for (int nt = 0; nt < 4; nt++) {
            const int c0 = colBase + wn * 32 + nt * 8 + cq * 2;
            float2 b2 = *(const float2*)&bias[c0];
            float2 o;
            o.x = acc[mt][nt][0] + b2.x;
            o.y = acc[mt][nt][1] + b2.y;
            *(float2*)&C[(size_t)r0 * N + c0] = o;
            o.x = acc[mt][nt][2] + b2.x;
            o.y = acc[mt][nt][3] + b2.y;
            *(float2*)&C[(size_t)(r0 + 8) * N + c0] = o;
        }
    }
}

// ---------------------------------------------------------------------------
// Per-(s,h): RMS-norm q,k, RoPE q,k, scatter q,k,v into [h][s][d].
// ---------------------------------------------------------------------------
__global__ void rmsrope_kernel(const float* __restrict__ nq, const float* __restrict__ nk,
                               const float* __restrict__ naq, const float* __restrict__ nak,
                               const float* __restrict__ cosT, const float* __restrict__ sinT)
{
    const int s = blockIdx.x;
    const int h = blockIdx.y;
    const int d = threadIdx.x;

    const float* row = g_QKV + (size_t)s * E3;
    float q = row[h * HD + d];
    float k = row[DM + h * HD + d];
    float v = row[2 * DM + h * HD + d];

    float qq = q * q, kk = k * k;
#pragma unroll
    for (int off = 16; off; off >>= 1) {
        qq += __shfl_xor_sync(0xffffffffu, qq, off);
        kk += __shfl_xor_sync(0xffffffffu, kk, off);
    }
    __shared__ float wq[4], wk[4];
    const int wid = d >> 5, lane = d & 31;
    if (lane == 0) { wq[wid] = qq; wk[wid] = kk; }
    __syncthreads();
    const float sq = wq[0] + wq[1] + wq[2] + wq[3];
    const float sk = wk[0] + wk[1] + wk[2] + wk[3];
    const float rq = rsqrtf(sq * (1.f / 128.f) + 1e-6f);
    const float rk = rsqrtf(sk * (1.f / 128.f) + 1e-6f);

    const bool txt = (s < ST);
    const float qw = txt ? naq[d] : nq[d];
    const float kw = txt ? nak[d] : nk[d];

    __shared__ float qb[128], kb[128];
    qb[d] = q * rq * qw;
    kb[d] = k * rk * kw;

    const size_t base = ((size_t)h * SS + s) * HD;
    g_V[base + d] = v;
    __syncthreads();

    if (d < 64) {
        const float c = cosT[s * 64 + d];
        const float sn = sinT[s * 64 + d];
        float q1 = qb[2 * d], q2 = qb[2 * d + 1];
        g_Q[base + 2 * d]     = q1 * c - q2 * sn;
        g_Q[base + 2 * d + 1] = q2 * c + q1 * sn;
        float k1 = kb[2 * d], k2 = kb[2 * d + 1];
        g_K[base + 2 * d]     = k1 * c - k2 * sn;
        g_K[base + 2 * d + 1] = k2 * c + k1 * sn;
    }
}

// ---------------------------------------------------------------------------
// Flash attention, tf32 tensor cores. BQ=128, BKV=64, 256 threads = 8 warps.
// S-mma: warp tile 64(q) x 16(kv); PV-mma: warp tile 64(q) x 32(d).
// Smem floats: Qs[128][132], Ks[64][132], Vs[128][68] (d-major, kv XOR-swizzled),
//              Ps[128][68], redmax[4][128], redsum[4][128], m_s[128], l_s[128].
// ---------------------------------------------------------------------------
#define OFF_KS   16896
#define OFF_VS   25344
#define OFF_PS   34048
#define OFF_RMAX 42752
#define OFF_RSUM 43264
#define OFF_MS   43776
#define OFF_LS   43904
#define ATTN_SMEM (44032 * 4)

__global__ void __launch_bounds__(256, 1) attn_tf32()
{
    extern __shared__ float sm[];
    float* Qs = sm;
    float* Ks = sm + OFF_KS;
    float* Vs = sm + OFF_VS;
    float* Ps = sm + OFF_PS;
    float* redmax = sm + OFF_RMAX;
    float* redsum = sm + OFF_RSUM;
    float* m_s = sm + OFF_MS;
    float* l_s = sm + OFF_LS;

    const int tid  = threadIdx.x;
    const int lane = tid & 31;
    const int wid  = tid >> 5;
    const int wm   = wid >> 2;   // 0..1
    const int wn   = wid & 3;    // 0..3
    const int rl   = lane >> 2;  // 0..7
    const int cq   = lane & 3;   // 0..3
    const int h    = blockIdx.y;
    const int q0   = blockIdx.x * 128;

    const float* Qg = g_Q + ((size_t)h * SS + q0) * HD;
    const float* Kg = g_K + (size_t)h * SS * HD;
    const float* Vg = g_V + (size_t)h * SS * HD;

    if (tid < 128) { m_s[tid] = -1e30f; l_s[tid] = 0.f; }

    // load Q tile (row-major, tf32)
#pragma unroll
    for (int it = 0; it < 16; it++) {
        int idx = tid + it * 256;
        int r = idx >> 5;
        int d4 = (idx & 31) * 4;
        float4 v = *(const float4*)&Qg[(size_t)r * HD + d4];
        float* p = &Qs[r * 132 + d4];
        p[0] = to_tf32(v.x); p[1] = to_tf32(v.y);
        p[2] = to_tf32(v.z); p[3] = to_tf32(v.w);
    }

    float oacc[4][4][4];
#pragma unroll
    for (int mt = 0; mt < 4; mt++)
#pragma unroll
        for (int nt = 0; nt < 4; nt++)
#pragma unroll
            for (int e = 0; e < 4; e++) oacc[mt][nt][e] = 0.f;

    for (int kt = 0; kt < SS; kt += 64) {
        __syncthreads();
        // K tile (row-major, tf32)
#pragma unroll
        for (int it = 0; it < 8; it++) {
            int idx = tid + it * 256;
            int r = idx >> 5;
            int d4 = (idx & 31) * 4;
            float4 v = *(const float4*)&Kg[(size_t)(kt + r) * HD + d4];
            float* p = &Ks[r * 132 + d4];
            p[0] = to_tf32(v.x); p[1] = to_tf32(v.y);
            p[2] = to_tf32(v.z); p[3] = to_tf32(v.w);
        }
        // V tile transposed: Vs[d][kv ^ 4*((d>>2)&7)]
#pragma unroll
        for (int it = 0; it < 8; it++) {
            int idx = tid + it * 256;
            int r = idx >> 5;              // kv 0..63
            int d4 = (idx & 31) * 4;
            float4 v = *(const float4*)&Vg[(size_t)(kt + r) * HD + d4];
            int rs = r ^ (((d4 >> 2) & 7) * 4);
            Vs[(d4 + 0) * 68 + rs] = to_tf32(v.x);
            Vs[(d4 + 1) * 68 + rs] = to_tf32(v.y);
            Vs[(d4 + 2) * 68 + rs] = to_tf32(v.z);
            Vs[(d4 + 3) * 68 + rs] = to_tf32(v.w);
        }
        __syncthreads();

        // ---- S = Q K^T ----
        float sc[4][2][4];
#pragma unroll
        for (int mt = 0; mt < 4; mt++)
#pragma unroll
            for (int nt = 0; nt < 2; nt++)
#pragma unroll
                for (int e = 0; e < 4; e++) sc[mt][nt][e] = 0.f;

#pragma unroll
        for (int kk = 0; kk < 128; kk += 8) {
            unsigned af[4][4];
#pragma unroll
            for (int mt = 0; mt < 4; mt++) {
                const float* ap = &Qs[(wm * 64 + mt * 16 + rl) * 132 + kk + cq];
                af[mt][0] = __float_as_uint(ap[0]);
                af[mt][1] = __float_as_uint(ap[8 * 132]);
                af[mt][2] = __float_as_uint(ap[4]);
                af[mt][3] = __float_as_uint(ap[8 * 132 + 4]);
            }
            unsigned bf[2][2];
#pragma unroll
            for (int nt = 0; nt < 2; nt++) {
                const float* bp = &Ks[(wn * 16 + nt * 8 + rl) * 132 + kk + cq];
                bf[nt][0] = __float_as_uint(bp[0]);
                bf[nt][1] = __float_as_uint(bp[4]);
            }
#pragma unroll
            for (int mt = 0; mt < 4; mt++)
#pragma unroll
                for (int nt = 0; nt < 2; nt++)
                    mma_tf32(sc[mt][nt], af[mt], bf[nt]);
        }

        // ---- softmax: warp-level row max ----
#pragma unroll
        for (int mt = 0; mt < 4; mt++) {
#pragma unroll
            for (int nt = 0; nt < 2; nt++)
#pragma unroll
                for (int e = 0; e < 4; e++) sc[mt][nt][e] *= ATTN_SCALE;
            float v0 = fmaxf(fmaxf(sc[mt][0][0], sc[mt][0][1]),
                             fmaxf(sc[mt][1][0], sc[mt][1][1]));
            float v1 = fmaxf(fmaxf(sc[mt][0][2], sc[mt][0][3]),
                             fmaxf(sc[mt][1][2], sc[mt][1][3]));
            v0 = fmaxf(v0, __shfl_xor_sync(0xffffffffu, v0, 1));
            v0 = fmaxf(v0, __shfl_xor_sync(0xffffffffu, v0, 2));
            v1 = fmaxf(v1, __shfl_xor_sync(0xffffffffu, v1, 1));
            v1 = fmaxf(v1, __shfl_xor_sync(0xffffffffu, v1, 2));
            if (cq == 0) {
                const int r0 = wm * 64 + mt * 16 + rl;
                redmax[wn * 128 + r0] = v0;
                redmax[wn * 128 + r0 + 8] = v1;
            }
        }
        __syncthreads();

        float fs[4][2];
#pragma unroll
        for (int mt = 0; mt < 4; mt++) {
            const int r0 = wm * 64 + mt * 16 + rl;
            const int r1 = r0 + 8;
            float mold0 = m_s[r0], mold1 = m_s[r1];
            float mn0 = fmaxf(fmaxf(fmaxf(redmax[r0], redmax[128 + r0]),
                                    fmaxf(redmax[256 + r0], redmax[384 + r0])), mold0);
            float mn1 = fmaxf(fmaxf(fmaxf(redmax[r1], redmax[128 + r1]),
                                    fmaxf(redmax[256 + r1], redmax[384 + r1])), mold1);
            fs[mt][0] = __expf(mold0 - mn0);
            fs[mt][1] = __expf(mold1 - mn1);

            float p00 = __expf(sc[mt][0][0] - mn0);
            float p01 = __expf(sc[mt][0][1] - mn0);
            float p10 = __expf(sc[mt][1][0] - mn0);
            float p11 = __expf(sc[mt][1][1] - mn0);
            float p02 = __expf(sc[mt][0][2] - mn1);
            float p03 = __expf(sc[mt][0][3] - mn1);
            float p12 = __expf(sc[mt][1][2] - mn1);
            float p13 = __expf(sc[mt][1][3] - mn1);

            float s0 = p00 + p01 + p10 + p11;
            float s1 = p02 + p03 + p12 + p13;
            s0 += __shfl_xor_sync(0xffffffffu, s0, 1);
            s0 += __shfl_xor_sync(0xffffffffu, s0, 2);
            s1 += __shfl_xor_sync(0xffffffffu, s1, 1);
            s1 += __shfl_xor_sync(0xffffffffu, s1, 2);
            if (cq == 0) {
                redsum[wn * 128 + r0] = s0;
                redsum[wn * 128 + r1] = s1;
            }

            // store P (tf32) rows r0, r1
            const int c0 = wn * 16 + cq * 2;
            float2 t;
            t.x = to_tf32(p00); t.y = to_tf32(p01);
            *(float2*)&Ps[r0 * 68 + c0] = t;
            t.x = to_tf32(p10); t.y = to_tf32(p11);
            *(float2*)&Ps[r0 * 68 + c0 + 8] = t;
            t.x = to_tf32(p02); t.y = to_tf32(p03);
            *(float2*)&Ps[r1 * 68 + c0] = t;
            t.x = to_tf32(p12); t.y = to_tf32(p13);
            *(float2*)&Ps[r1 * 68 + c0 + 8] = t;

            // rescale O accumulator
#pragma unroll
            for (int nt = 0; nt < 4; nt++) {
                oacc[mt][nt][0] *= fs[mt][0];
                oacc[mt][nt][1] *= fs[mt][0];
                oacc[mt][nt][2] *= fs[mt][1];
                oacc[mt][nt][3] *= fs[mt][1];
            }
        }
        __syncthreads();

        // running m/l update (one thread per row)
        if (tid < 128) {
            float mold = m_s[tid];
            float mn = fmaxf(fmaxf(fmaxf(redmax[tid], redmax[128 + tid]),
                                   fmaxf(redmax[256 + tid], redmax[384 + tid])), mold);
            l_s[tid] = l_s[tid] * __expf(mold - mn) +
                       (redsum[tid] + redsum[128 + tid] + redsum[256 + tid] + redsum[384 + tid]);
            m_s[tid] = mn;
        }

        // ---- O += P V ----
#pragma unroll
        for (int kk = 0; kk < 64; kk += 8) {
            unsigned af[4][4];
#pragma unroll
            for (int mt = 0; mt < 4; mt++) {
                const float* ap = &Ps[(wm * 64 + mt * 16 + rl) * 68 + kk + cq];
                af[mt][0] = __float_as_uint(ap[0]);
                af[mt][1] = __float_as_uint(ap[8 * 68]);
                af[mt][2] = __float_as_uint(ap[4]);
                af[mt][3] = __float_as_uint(ap[8 * 68 + 4]);
            }
            unsigned bf[4][2];
#pragma unroll
            for (int nt = 0; nt < 4; nt++) {
                const int n = wn * 32 + nt * 8 + rl;
                const int msk = ((n >> 2) & 7) * 4;
                bf[nt][0] = __float_as_uint(Vs[n * 68 + ((kk + cq) ^ msk)]);
                bf[nt][1] = __float_as_uint(Vs[n * 68 + ((kk + 4 + cq) ^ msk)]);
            }
#pragma unroll
            for (int mt = 0; mt < 4; mt++)
#pragma unroll
                for (int nt = 0; nt < 4; nt++)
                    mma_tf32(oacc[mt][nt], af[mt], bf[nt]);
        }
    }
    __syncthreads();

    // epilogue: divide by l, write [s][h*128+d]
#pragma unroll
    for (int mt = 0; mt < 4; mt++) {
        const int r0 = wm * 64 + mt * 16 + rl;
        const int r1 = r0 + 8;
        const float il0 = 1.f / l_s[r0];
        const float il1 = 1.f / l_s[r1];
#pragma unroll
        for (int nt = 0; nt < 4; nt++) {
            const int col = wn * 32 + nt * 8 + cq * 2;
            float2 o;
            o.x = oacc[mt][nt][0] * il0;
            o.y = oacc[mt][nt][1] * il0;
            *(float2*)&g_O[(size_t)(q0 + r0) * (NH * HD) + h * HD + col] = o;
            o.x = oacc[mt][nt][2] * il1;
            o.y = oacc[mt][nt][3] * il1;
            *(float2*)&g_O[(size_t)(q0 + r1) * (NH * HD) + h * HD + col] = o;
        }
    }
}

// ---------------------------------------------------------------------------
extern "C" void kernel_launch(void* const* d_in, const int* in_sizes, int n_in,
                              void* d_out, int out_size)
{
    (void)in_sizes; (void)n_in; (void)out_size;
    const float* hidden = (const float*)d_in[0];
    const float* enc    = (const float*)d_in[1];
    const float* cosT   = (const float*)d_in[2];
    const float* sinT   = (const float*)d_in[3];
    const float* w_qkv  = (const float*)d_in[4];
    const float* b_qkv  = (const float*)d_in[5];
    const float* w_add  = (const float*)d_in[6];
    const float* b_add  = (const float*)d_in[7];
    const float* nq_w   = (const float*)d_in[8];
    const float* nk_w   = (const float*)d_in[9];
    const float* naq_w  = (const float*)d_in[10];
    const float* nak_w  = (const float*)d_in[11];
    const float* w_out  = (const float*)d_in[12];
    const float* b_out  = (const float*)d_in[13];
    const float* w_ao   = (const float*)d_in[14];
    const float* b_ao   = (const float*)d_in[15];
    float* out = (float*)d_out;

    float *qkv = nullptr, *obuf = nullptr;
    cudaGetSymbolAddress((void**)&qkv, g_QKV);
    cudaGetSymbolAddress((void**)&obuf, g_O);
    cudaFuncSetAttribute(attn_tf32, cudaFuncAttributeMaxDynamicSharedMemorySize, ATTN_SMEM);

    // QKV projections (text rows use w_add; image rows use w_qkv)
    gemm_tf32<<<dim3(E3 / 128, ST / 128), 256>>>(enc, w_add, b_add, qkv, DM, E3);
    gemm_tf32<<<dim3(E3 / 128, SI / 128), 256>>>(hidden, w_qkv, b_qkv,
                                                 qkv + (size_t)ST * E3, DM, E3);
    // RMS norm + RoPE + scatter to [h][s][d]
    rmsrope_kernel<<<dim3(SS, NH), 128>>>(nq_w, nk_w, naq_w, nak_w, cosT, sinT);
    // attention
    attn_tf32<<<dim3(SS / 128, NH), 256, ATTN_SMEM>>>();
    // output projections: img_out first, then txt_out
    gemm_tf32<<<dim3(DM / 128, SI / 128), 256>>>(obuf + (size_t)ST * DM, w_out, b_out,
                                                 out, DM, DM);
    gemm_tf32<<<dim3(DM / 128, ST / 128), 256>>>(obuf, w_ao, b_ao,
                                                 out + (size_t)SI * DM, DM, DM);
}

// round 12
// speedup vs baseline: 2.9381x; 1.1372x over previous
#include <cuda_runtime.h>
#include <cstdint>

#define ST 512
#define SI 2048
#define SS 2560
#define DM 3072
#define NH 24
#define HD 128
#define E3 9216
#define ATTN_SCALE 0.08838834764831845f  // 1/sqrt(128)

// ---------------- scratch (device globals: no allocations allowed) ----------
__device__ float g_QKV[(size_t)SS * E3];      // [s][9216]
__device__ float g_Q[(size_t)NH * SS * HD];   // [h][s][d]
__device__ float g_K[(size_t)NH * SS * HD];
__device__ float g_V[(size_t)NH * SS * HD];
__device__ float g_O[(size_t)SS * NH * HD];   // [s][h*128+d]

__device__ __forceinline__ uint32_t smem_u32(const void* p) {
    uint32_t a;
    asm("{ .reg .u64 t; cvta.to.shared.u64 t, %1; cvt.u32.u64 %0, t; }" : "=r"(a) : "l"(p));
    return a;
}
__device__ __forceinline__ float to_tf32(float x) {
    float r;
    asm("cvt.rna.tf32.f32 %0, %1;" : "=f"(r) : "f"(x));
    return r;
}
__device__ __forceinline__ unsigned tf32_bits(float x) {
    return __float_as_uint(to_tf32(x));
}
__device__ __forceinline__ void mma_tf32(float (&c)[4], const unsigned (&a)[4],
                                         const unsigned (&b)[2]) {
    asm volatile(
        "mma.sync.aligned.m16n8k8.row.col.f32.tf32.tf32.f32 "
        "{%0,%1,%2,%3}, {%4,%5,%6,%7}, {%8,%9}, {%0,%1,%2,%3};\n"
        : "+f"(c[0]), "+f"(c[1]), "+f"(c[2]), "+f"(c[3])
        : "r"(a[0]), "r"(a[1]), "r"(a[2]), "r"(a[3]), "r"(b[0]), "r"(b[1]));
}
#define CP16(dst, src) \
    asm volatile("cp.async.cg.shared.global [%0], [%1], 16;" :: "r"(dst), "l"(src))
#define CP_COMMIT() asm volatile("cp.async.commit_group;" ::: "memory")
#define CP_WAIT2()  asm volatile("cp.async.wait_group 2;" ::: "memory")

// ---------------------------------------------------------------------------
// Pipelined tf32 GEMM: C[M,N] = A[M,K] * B[N,K]^T + bias[N]
// CTA tile 128x256, BK=16, 256 threads = 8 warps (2x4), warp tile 64x64.
// 4 smem buffers, 3-stage cp.async prefetch, one __syncthreads per slab.
// Smem per stage: A 128x20 + B 256x20 floats (stride 20 -> conflict-free frags).
// ---------------------------------------------------------------------------
#define STAGE_FLOATS 7680            // (128 + 256) * 20
#define STAGE_BYTES  30720
#define GEMM_SMEM    (4 * STAGE_BYTES)

__global__ void __launch_bounds__(256, 1) gemm_tf32p(
    const float* __restrict__ A, const float* __restrict__ B,
    const float* __restrict__ bias, float* __restrict__ C,
    int K, int N)
{
    extern __shared__ float smf[];
    const uint32_t smb = smem_u32(smf);

    const int tid  = threadIdx.x;
    const int lane = tid & 31;
    const int wid  = tid >> 5;
    const int wm   = wid >> 2;   // 0..1 : 64 M-rows
    const int wn   = wid & 3;    // 0..3 : 64 N-cols
    const int rl   = lane >> 2;  // 0..7
    const int cq   = lane & 3;   // 0..3
    const int rowBase = blockIdx.x * 128;
    const int colBase = blockIdx.y * 256;

    const float* Ag = A + (size_t)rowBase * K;
    const float* Bg = B + (size_t)colBase * K;

    const int nSlab = K >> 4;    // K / 16

    // loader: thread t copies 2 A-float4s + 4 B-float4s per stage
    const int lr = tid >> 2;          // 0..63
    const int lk4 = (tid & 3) * 4;    // 0,4,8,12
    auto load_stage = [&](int s, uint32_t bufb) {
        const int kt = s * 16;
#pragma unroll
        for (int j = 0; j < 2; j++) {
            const int r = lr + j * 64;
            CP16(bufb + (uint32_t)(r * 80 + lk4 * 4),
                 (const char*)(Ag + (size_t)r * K + kt + lk4));
        }
        const uint32_t bb = bufb + 10240u;
#pragma unroll
        for (int j = 0; j < 4; j++) {
            const int r = lr + j * 64;
            CP16(bb + (uint32_t)(r * 80 + lk4 * 4),
                 (const char*)(Bg + (size_t)r * K + kt + lk4));
        }
    };

    float acc[4][8][4];
#pragma unroll
    for (int mt = 0; mt < 4; mt++)
#pragma unroll
        for (int nt = 0; nt < 8; nt++)
#pragma unroll
            for (int e = 0; e < 4; e++) acc[mt][nt][e] = 0.f;

    // prologue: 3 stages in flight
    load_stage(0, smb);                 CP_COMMIT();
    load_stage(1, smb + STAGE_BYTES);   CP_COMMIT();
    load_stage(2, smb + 2 * STAGE_BYTES); CP_COMMIT();

    for (int s = 0; s < nSlab; s++) {
        CP_WAIT2();                     // stage s ready
        __syncthreads();
        if (s + 3 < nSlab)
            load_stage(s + 3, smb + (uint32_t)((s + 3) & 3) * STAGE_BYTES);
        CP_COMMIT();

        const float* As = smf + (s & 3) * STAGE_FLOATS;
        const float* Bs = As + 2560;
#pragma unroll
        for (int kk = 0; kk < 16; kk += 8) {
            unsigned af[4][4];
#pragma unroll
            for (int mt = 0; mt < 4; mt++) {
                const float* ap = &As[(wm * 64 + mt * 16 + rl) * 20 + kk + cq];
                af[mt][0] = tf32_bits(ap[0]);
                af[mt][1] = tf32_bits(ap[160]);
                af[mt][2] = tf32_bits(ap[4]);
                af[mt][3] = tf32_bits(ap[164]);
            }
            unsigned bf[8][2];
#pragma unroll
            for (int nt = 0; nt < 8; nt++) {
                const float* bp = &Bs[(wn * 64 + nt * 8 + rl) * 20 + kk + cq];
                bf[nt][0] = tf32_bits(bp[0]);
                bf[nt][1] = tf32_bits(bp[4]);
            }
#pragma unroll
            for (int mt = 0; mt < 4; mt++)
#pragma unroll
                for (int nt = 0; nt < 8; nt++)
                    mma_tf32(acc[mt][nt], af[mt], bf[nt]);
        }
    }

    // epilogue
#pragma unroll
    for (int mt = 0; mt < 4; mt++) {
        const int r0 = rowBase + wm * 64 + mt * 16 + rl;
#pragma unroll
        for (int nt = 0; nt < 8; nt++) {
            const int c0 = colBase + wn * 64 + nt * 8 + cq * 2;
            float2 b2 = *(const float2*)&bias[c0];
            float2 o;
            o.x = acc[mt][nt][0] + b2.x;
            o.y = acc[mt][nt][1] + b2.y;
            *(float2*)&C[(size_t)r0 * N + c0] = o;
            o.x = acc[mt][nt][2] + b2.x;
            o.y = acc[mt][nt][3] + b2.y;
            *(float2*)&C[(size_t)(r0 + 8) * N + c0] = o;
        }
    }
}

// ---------------------------------------------------------------------------
// Per-(s,h): RMS-norm q,k, RoPE q,k, scatter q,k,v into [h][s][d].
// ---------------------------------------------------------------------------
__global__ void rmsrope_kernel(const float* __restrict__ nq, const float* __restrict__ nk,
                               const float* __restrict__ naq, const float* __restrict__ nak,
                               const float* __restrict__ cosT, const float* __restrict__ sinT)
{
    const int s = blockIdx.x;
    const int h = blockIdx.y;
    const int d = threadIdx.x;

    const float* row = g_QKV + (size_t)s * E3;
    float q = row[h * HD + d];
    float k = row[DM + h * HD + d];
    float v = row[2 * DM + h * HD + d];

    float qq = q * q, kk = k * k;
#pragma unroll
    for (int off = 16; off; off >>= 1) {
        qq += __shfl_xor_sync(0xffffffffu, qq, off);
        kk += __shfl_xor_sync(0xffffffffu, kk, off);
    }
    __shared__ float wq[4], wk[4];
    const int wid = d >> 5, lane = d & 31;
    if (lane == 0) { wq[wid] = qq; wk[wid] = kk; }
    __syncthreads();
    const float sq = wq[0] + wq[1] + wq[2] + wq[3];
    const float sk = wk[0] + wk[1] + wk[2] + wk[3];
    const float rq = rsqrtf(sq * (1.f / 128.f) + 1e-6f);
    const float rk = rsqrtf(sk * (1.f / 128.f) + 1e-6f);

    const bool txt = (s < ST);
    const float qw = txt ? naq[d] : nq[d];
    const float kw = txt ? nak[d] : nk[d];

    __shared__ float qb[128], kb[128];
    qb[d] = q * rq * qw;
    kb[d] = k * rk * kw;

    const size_t base = ((size_t)h * SS + s) * HD;
    g_V[base + d] = v;
    __syncthreads();

    if (d < 64) {
        const float c = cosT[s * 64 + d];
        const float sn = sinT[s * 64 + d];
        float q1 = qb[2 * d], q2 = qb[2 * d + 1];
        g_Q[base + 2 * d]     = q1 * c - q2 * sn;
        g_Q[base + 2 * d + 1] = q2 * c + q1 * sn;
        float k1 = kb[2 * d], k2 = kb[2 * d + 1];
        g_K[base + 2 * d]     = k1 * c - k2 * sn;
        g_K[base + 2 * d + 1] = k2 * c + k1 * sn;
    }
}

// ---------------------------------------------------------------------------
// Flash attention, tf32 tensor cores (R4 version, unchanged — passed at 856us).
// ---------------------------------------------------------------------------
#define OFF_KS   16896
#define OFF_VS   25344
#define OFF_PS   34048
#define OFF_RMAX 42752
#define OFF_RSUM 43264
#define OFF_MS   43776
#define OFF_LS   43904
#define ATTN_SMEM (44032 * 4)

__global__ void __launch_bounds__(256, 1) attn_tf32()
{
    extern __shared__ float sm[];
    float* Qs = sm;
    float* Ks = sm + OFF_KS;
    float* Vs = sm + OFF_VS;
    float* Ps = sm + OFF_PS;
    float* redmax = sm + OFF_RMAX;
    float* redsum = sm + OFF_RSUM;
    float* m_s = sm + OFF_MS;
    float* l_s = sm + OFF_LS;

    const int tid  = threadIdx.x;
    const int lane = tid & 31;
    const int wid  = tid >> 5;
    const int wm   = wid >> 2;
    const int wn   = wid & 3;
    const int rl   = lane >> 2;
    const int cq   = lane & 3;
    const int h    = blockIdx.y;
    const int q0   = blockIdx.x * 128;

    const float* Qg = g_Q + ((size_t)h * SS + q0) * HD;
    const float* Kg = g_K + (size_t)h * SS * HD;
    const float* Vg = g_V + (size_t)h * SS * HD;

    if (tid < 128) { m_s[tid] = -1e30f; l_s[tid] = 0.f; }

#pragma unroll
    for (int it = 0; it < 16; it++) {
        int idx = tid + it * 256;
        int r = idx >> 5;
        int d4 = (idx & 31) * 4;
        float4 v = *(const float4*)&Qg[(size_t)r * HD + d4];
        float* p = &Qs[r * 132 + d4];
        p[0] = to_tf32(v.x); p[1] = to_tf32(v.y);
        p[2] = to_tf32(v.z); p[3] = to_tf32(v.w);
    }

    float oacc[4][4][4];
#pragma unroll
    for (int mt = 0; mt < 4; mt++)
#pragma unroll
        for (int nt = 0; nt < 4; nt++)
#pragma unroll
            for (int e = 0; e < 4; e++) oacc[mt][nt][e] = 0.f;

    for (int kt = 0; kt < SS; kt += 64) {
        __syncthreads();
#pragma unroll
        for (int it = 0; it < 8; it++) {
            int idx = tid + it * 256;
            int r = idx >> 5;
            int d4 = (idx & 31) * 4;
            float4 v = *(const float4*)&Kg[(size_t)(kt + r) * HD + d4];
            float* p = &Ks[r * 132 + d4];
            p[0] = to_tf32(v.x); p[1] = to_tf32(v.y);
            p[2] = to_tf32(v.z); p[3] = to_tf32(v.w);
        }
#pragma unroll
        for (int it = 0; it < 8; it++) {
            int idx = tid + it * 256;
            int r = idx >> 5;
            int d4 = (idx & 31) * 4;
            float4 v = *(const float4*)&Vg[(size_t)(kt + r) * HD + d4];
            int rs = r ^ (((d4 >> 2) & 7) * 4);
            Vs[(d4 + 0) * 68 + rs] = to_tf32(v.x);
            Vs[(d4 + 1) * 68 + rs] = to_tf32(v.y);
            Vs[(d4 + 2) * 68 + rs] = to_tf32(v.z);
            Vs[(d4 + 3) * 68 + rs] = to_tf32(v.w);
        }
        __syncthreads();

        float sc[4][2][4];
#pragma unroll
        for (int mt = 0; mt < 4; mt++)
#pragma unroll
            for (int nt = 0; nt < 2; nt++)
#pragma unroll
                for (int e = 0; e < 4; e++) sc[mt][nt][e] = 0.f;

#pragma unroll
        for (int kk = 0; kk < 128; kk += 8) {
            unsigned af[4][4];
#pragma unroll
            for (int mt = 0; mt < 4; mt++) {
                const float* ap = &Qs[(wm * 64 + mt * 16 + rl) * 132 + kk + cq];
                af[mt][0] = __float_as_uint(ap[0]);
                af[mt][1] = __float_as_uint(ap[8 * 132]);
                af[mt][2] = __float_as_uint(ap[4]);
                af[mt][3] = __float_as_uint(ap[8 * 132 + 4]);
            }
            unsigned bf[2][2];
#pragma unroll
            for (int nt = 0; nt < 2; nt++) {
                const float* bp = &Ks[(wn * 16 + nt * 8 + rl) * 132 + kk + cq];
                bf[nt][0] = __float_as_uint(bp[0]);
                bf[nt][1] = __float_as_uint(bp[4]);
            }
#pragma unroll
            for (int mt = 0; mt < 4; mt++)
#pragma unroll
                for (int nt = 0; nt < 2; nt++)
                    mma_tf32(sc[mt][nt], af[mt], bf[nt]);
        }

#pragma unroll
        for (int mt = 0; mt < 4; mt++) {
#pragma unroll
            for (int nt = 0; nt < 2; nt++)
#pragma unroll
                for (int e = 0; e < 4; e++) sc[mt][nt][e] *= ATTN_SCALE;
            float v0 = fmaxf(fmaxf(sc[mt][0][0], sc[mt][0][1]),
                             fmaxf(sc[mt][1][0], sc[mt][1][1]));
            float v1 = fmaxf(fmaxf(sc[mt][0][2], sc[mt][0][3]),
                             fmaxf(sc[mt][1][2], sc[mt][1][3]));
            v0 = fmaxf(v0, __shfl_xor_sync(0xffffffffu, v0, 1));
            v0 = fmaxf(v0, __shfl_xor_sync(0xffffffffu, v0, 2));
            v1 = fmaxf(v1, __shfl_xor_sync(0xffffffffu, v1, 1));
            v1 = fmaxf(v1, __shfl_xor_sync(0xffffffffu, v1, 2));
            if (cq == 0) {
                const int r0 = wm * 64 + mt * 16 + rl;
                redmax[wn * 128 + r0] = v0;
                redmax[wn * 128 + r0 + 8] = v1;
            }
        }
        __syncthreads();

        float fs[4][2];
#pragma unroll
        for (int mt = 0; mt < 4; mt++) {
            const int r0 = wm * 64 + mt * 16 + rl;
            const int r1 = r0 + 8;
            float mold0 = m_s[r0], mold1 = m_s[r1];
            float mn0 = fmaxf(fmaxf(fmaxf(redmax[r0], redmax[128 + r0]),
                                    fmaxf(redmax[256 + r0], redmax[384 + r0])), mold0);
            float mn1 = fmaxf(fmaxf(fmaxf(redmax[r1], redmax[128 + r1]),
                                    fmaxf(redmax[256 + r1], redmax[384 + r1])), mold1);
            fs[mt][0] = __expf(mold0 - mn0);
            fs[mt][1] = __expf(mold1 - mn1);

            float p00 = __expf(sc[mt][0][0] - mn0);
            float p01 = __expf(sc[mt][0][1] - mn0);
            float p10 = __expf(sc[mt][1][0] - mn0);
            float p11 = __expf(sc[mt][1][1] - mn0);
            float p02 = __expf(sc[mt][0][2] - mn1);
            float p03 = __expf(sc[mt][0][3] - mn1);
            float p12 = __expf(sc[mt][1][2] - mn1);
            float p13 = __expf(sc[mt][1][3] - mn1);

            float s0 = p00 + p01 + p10 + p11;
            float s1 = p02 + p03 + p12 + p13;
            s0 += __shfl_xor_sync(0xffffffffu, s0, 1);
            s0 += __shfl_xor_sync(0xffffffffu, s0, 2);
            s1 += __shfl_xor_sync(0xffffffffu, s1, 1);
            s1 += __shfl_xor_sync(0xffffffffu, s1, 2);
            if (cq == 0) {
                redsum[wn * 128 + r0] = s0;
                redsum[wn * 128 + r1] = s1;
            }

            const int c0 = wn * 16 + cq * 2;
            float2 t;
            t.x = to_tf32(p00); t.y = to_tf32(p01);
            *(float2*)&Ps[r0 * 68 + c0] = t;
            t.x = to_tf32(p10); t.y = to_tf32(p11);
            *(float2*)&Ps[r0 * 68 + c0 + 8] = t;
            t.x = to_tf32(p02); t.y = to_tf32(p03);
            *(float2*)&Ps[r1 * 68 + c0] = t;
            t.x = to_tf32(p12); t.y = to_tf32(p13);
            *(float2*)&Ps[r1 * 68 + c0 + 8] = t;

#pragma unroll
            for (int nt = 0; nt < 4; nt++) {
                oacc[mt][nt][0] *= fs[mt][0];
                oacc[mt][nt][1] *= fs[mt][0];
                oacc[mt][nt][2] *= fs[mt][1];
                oacc[mt][nt][3] *= fs[mt][1];
            }
        }
        __syncthreads();

        if (tid < 128) {
            float mold = m_s[tid];
            float mn = fmaxf(fmaxf(fmaxf(redmax[tid], redmax[128 + tid]),
                                   fmaxf(redmax[256 + tid], redmax[384 + tid])), mold);
            l_s[tid] = l_s[tid] * __expf(mold - mn) +
                       (redsum[tid] + redsum[128 + tid] + redsum[256 + tid] + redsum[384 + tid]);
            m_s[tid] = mn;
        }

#pragma unroll
        for (int kk = 0; kk < 64; kk += 8) {
            unsigned af[4][4];
#pragma unroll
            for (int mt = 0; mt < 4; mt++) {
                const float* ap = &Ps[(wm * 64 + mt * 16 + rl) * 68 + kk + cq];
                af[mt][0] = __float_as_uint(ap[0]);
                af[mt][1] = __float_as_uint(ap[8 * 68]);
                af[mt][2] = __float_as_uint(ap[4]);
                af[mt][3] = __float_as_uint(ap[8 * 68 + 4]);
            }
            unsigned bf[4][2];
#pragma unroll
            for (int nt = 0; nt < 4; nt++) {
                const int n = wn * 32 + nt * 8 + rl;
                const int msk = ((n >> 2) & 7) * 4;
                bf[nt][0] = __float_as_uint(Vs[n * 68 + ((kk + cq) ^ msk)]);
                bf[nt][1] = __float_as_uint(Vs[n * 68 + ((kk + 4 + cq) ^ msk)]);
            }
#pragma unroll
            for (int mt = 0; mt < 4; mt++)
#pragma unroll
                for (int nt = 0; nt < 4; nt++)
                    mma_tf32(oacc[mt][nt], af[mt], bf[nt]);
        }
    }
    __syncthreads();

#pragma unroll
    for (int mt = 0; mt < 4; mt++) {
        const int r0 = wm * 64 + mt * 16 + rl;
        const int r1 = r0 + 8;
        const float il0 = 1.f / l_s[r0];
        const float il1 = 1.f / l_s[r1];
#pragma unroll
        for (int nt = 0; nt < 4; nt++) {
            const int col = wn * 32 + nt * 8 + cq * 2;
            float2 o;
            o.x = oacc[mt][nt][0] * il0;
            o.y = oacc[mt][nt][1] * il0;
            *(float2*)&g_O[(size_t)(q0 + r0) * (NH * HD) + h * HD + col] = o;
            o.x = oacc[mt][nt][2] * il1;
            o.y = oacc[mt][nt][3] * il1;
            *(float2*)&g_O[(size_t)(q0 + r1) * (NH * HD) + h * HD + col] = o;
        }
    }
}

// ---------------------------------------------------------------------------
extern "C" void kernel_launch(void* const* d_in, const int* in_sizes, int n_in,
                              void* d_out, int out_size)
{
    (void)in_sizes; (void)n_in; (void)out_size;
    const float* hidden = (const float*)d_in[0];
    const float* enc    = (const float*)d_in[1];
    const float* cosT   = (const float*)d_in[2];
    const float* sinT   = (const float*)d_in[3];
    const float* w_qkv  = (const float*)d_in[4];
    const float* b_qkv  = (const float*)d_in[5];
    const float* w_add  = (const float*)d_in[6];
    const float* b_add  = (const float*)d_in[7];
    const float* nq_w   = (const float*)d_in[8];
    const float* nk_w   = (const float*)d_in[9];
    const float* naq_w  = (const float*)d_in[10];
    const float* nak_w  = (const float*)d_in[11];
    const float* w_out  = (const float*)d_in[12];
    const float* b_out  = (const float*)d_in[13];
    const float* w_ao   = (const float*)d_in[14];
    const float* b_ao   = (const float*)d_in[15];
    float* out = (float*)d_out;

    float *qkv = nullptr, *obuf = nullptr;
    cudaGetSymbolAddress((void**)&qkv, g_QKV);
    cudaGetSymbolAddress((void**)&obuf, g_O);
    cudaFuncSetAttribute(attn_tf32, cudaFuncAttributeMaxDynamicSharedMemorySize, ATTN_SMEM);
    cudaFuncSetAttribute(gemm_tf32p, cudaFuncAttributeMaxDynamicSharedMemorySize, GEMM_SMEM);

    // QKV projections (text rows 0..511 use w_add; image rows use w_qkv)
    gemm_tf32p<<<dim3(ST / 128, E3 / 256), 256, GEMM_SMEM>>>(
        enc, w_add, b_add, qkv, DM, E3);
    gemm_tf32p<<<dim3(SI / 128, E3 / 256), 256, GEMM_SMEM>>>(
        hidden, w_qkv, b_qkv, qkv + (size_t)ST * E3, DM, E3);

    // RMS norm + RoPE + scatter to [h][s][d]
    rmsrope_kernel<<<dim3(SS, NH), 128>>>(nq_w, nk_w, naq_w, nak_w, cosT, sinT);

    // attention
    attn_tf32<<<dim3(SS / 128, NH), 256, ATTN_SMEM>>>();

    // output projections: img_out first, then txt_out
    gemm_tf32p<<<dim3(SI / 128, DM / 256), 256, GEMM_SMEM>>>(
        obuf + (size_t)ST * DM, w_out, b_out, out, DM, DM);
    gemm_tf32p<<<dim3(ST / 128, DM / 256), 256, GEMM_SMEM>>>(
        obuf, w_ao, b_ao, out + (size_t)SI * DM, DM, DM);
}

// round 14
// speedup vs baseline: 3.0845x; 1.0498x over previous
#include <cuda_runtime.h>
#include <cstdint>

#define ST 512
#define SI 2048
#define SS 2560
#define DM 3072
#define NH 24
#define HD 128
#define E3 9216
#define ATTN_SCALE 0.08838834764831845f  // 1/sqrt(128)

// ---------------- scratch (device globals: no allocations allowed) ----------
__device__ float g_QKV[(size_t)SS * E3];      // [s][9216]
__device__ float g_Q[(size_t)NH * SS * HD];   // [h][s][d]
__device__ float g_K[(size_t)NH * SS * HD];
__device__ float g_V[(size_t)NH * SS * HD];
__device__ float g_O[(size_t)SS * NH * HD];   // [s][h*128+d]

__device__ __forceinline__ uint32_t smem_u32(const void* p) {
    uint32_t a;
    asm("{ .reg .u64 t; cvta.to.shared.u64 t, %1; cvt.u32.u64 %0, t; }" : "=r"(a) : "l"(p));
    return a;
}
__device__ __forceinline__ float to_tf32(float x) {
    float r;
    asm("cvt.rna.tf32.f32 %0, %1;" : "=f"(r) : "f"(x));
    return r;
}
__device__ __forceinline__ unsigned tf32_bits(float x) {
    return __float_as_uint(to_tf32(x));
}
__device__ __forceinline__ void mma_tf32(float (&c)[4], const unsigned (&a)[4],
                                         const unsigned (&b)[2]) {
    asm volatile(
        "mma.sync.aligned.m16n8k8.row.col.f32.tf32.tf32.f32 "
        "{%0,%1,%2,%3}, {%4,%5,%6,%7}, {%8,%9}, {%0,%1,%2,%3};\n"
        : "+f"(c[0]), "+f"(c[1]), "+f"(c[2]), "+f"(c[3])
        : "r"(a[0]), "r"(a[1]), "r"(a[2]), "r"(a[3]), "r"(b[0]), "r"(b[1]));
}
#define CP16(dst, src) \
    asm volatile("cp.async.cg.shared.global [%0], [%1], 16;" :: "r"(dst), "l"(src))
#define CP_COMMIT() asm volatile("cp.async.commit_group;" ::: "memory")
#define CP_WAIT2()  asm volatile("cp.async.wait_group 2;" ::: "memory")
#define CP_WAIT1()  asm volatile("cp.async.wait_group 1;" ::: "memory")

// ---------------------------------------------------------------------------
// Pipelined tf32 GEMM: C[M,N] = A[M,K] * B[N,K]^T + bias[N]  (unchanged, R8)
// ---------------------------------------------------------------------------
#define STAGE_FLOATS 7680            // (128 + 256) * 20
#define STAGE_BYTES  30720
#define GEMM_SMEM    (4 * STAGE_BYTES)

__global__ void __launch_bounds__(256, 1) gemm_tf32p(
    const float* __restrict__ A, const float* __restrict__ B,
    const float* __restrict__ bias, float* __restrict__ C,
    int K, int N)
{
    extern __shared__ float smf[];
    const uint32_t smb = smem_u32(smf);

    const int tid  = threadIdx.x;
    const int lane = tid & 31;
    const int wid  = tid >> 5;
    const int wm   = wid >> 2;
    const int wn   = wid & 3;
    const int rl   = lane >> 2;
    const int cq   = lane & 3;
    const int rowBase = blockIdx.x * 128;
    const int colBase = blockIdx.y * 256;

    const float* Ag = A + (size_t)rowBase * K;
    const float* Bg = B + (size_t)colBase * K;

    const int nSlab = K >> 4;

    const int lr = tid >> 2;
    const int lk4 = (tid & 3) * 4;
    auto load_stage = [&](int s, uint32_t bufb) {
        const int kt = s * 16;
#pragma unroll
        for (int j = 0; j < 2; j++) {
            const int r = lr + j * 64;
            CP16(bufb + (uint32_t)(r * 80 + lk4 * 4),
                 (const char*)(Ag + (size_t)r * K + kt + lk4));
        }
        const uint32_t bb = bufb + 10240u;
#pragma unroll
        for (int j = 0; j < 4; j++) {
            const int r = lr + j * 64;
            CP16(bb + (uint32_t)(r * 80 + lk4 * 4),
                 (const char*)(Bg + (size_t)r * K + kt + lk4));
        }
    };

    float acc[4][8][4];
#pragma unroll
    for (int mt = 0; mt < 4; mt++)
#pragma unroll
        for (int nt = 0; nt < 8; nt++)
#pragma unroll
            for (int e = 0; e < 4; e++) acc[mt][nt][e] = 0.f;

    load_stage(0, smb);                   CP_COMMIT();
    load_stage(1, smb + STAGE_BYTES);     CP_COMMIT();
    load_stage(2, smb + 2 * STAGE_BYTES); CP_COMMIT();

    for (int s = 0; s < nSlab; s++) {
        CP_WAIT2();
        __syncthreads();
        if (s + 3 < nSlab)
            load_stage(s + 3, smb + (uint32_t)((s + 3) & 3) * STAGE_BYTES);
        CP_COMMIT();

        const float* As = smf + (s & 3) * STAGE_FLOATS;
        const float* Bs = As + 2560;
#pragma unroll
        for (int kk = 0; kk < 16; kk += 8) {
            unsigned af[4][4];
#pragma unroll
            for (int mt = 0; mt < 4; mt++) {
                const float* ap = &As[(wm * 64 + mt * 16 + rl) * 20 + kk + cq];
                af[mt][0] = tf32_bits(ap[0]);
                af[mt][1] = tf32_bits(ap[160]);
                af[mt][2] = tf32_bits(ap[4]);
                af[mt][3] = tf32_bits(ap[164]);
            }
            unsigned bf[8][2];
#pragma unroll
            for (int nt = 0; nt < 8; nt++) {
                const float* bp = &Bs[(wn * 64 + nt * 8 + rl) * 20 + kk + cq];
                bf[nt][0] = tf32_bits(bp[0]);
                bf[nt][1] = tf32_bits(bp[4]);
            }
#pragma unroll
            for (int mt = 0; mt < 4; mt++)
#pragma unroll
                for (int nt = 0; nt < 8; nt++)
                    mma_tf32(acc[mt][nt], af[mt], bf[nt]);
        }
    }

#pragma unroll
    for (int mt = 0; mt < 4; mt++) {
        const int r0 = rowBase + wm * 64 + mt * 16 + rl;
#pragma unroll
        for (int nt = 0; nt < 8; nt++) {
            const int c0 = colBase + wn * 64 + nt * 8 + cq * 2;
            float2 b2 = *(const float2*)&bias[c0];
            float2 o;
            o.x = acc[mt][nt][0] + b2.x;
            o.y = acc[mt][nt][1] + b2.y;
            *(float2*)&C[(size_t)r0 * N + c0] = o;
            o.x = acc[mt][nt][2] + b2.x;
            o.y = acc[mt][nt][3] + b2.y;
            *(float2*)&C[(size_t)(r0 + 8) * N + c0] = o;
        }
    }
}

// ---------------------------------------------------------------------------
// Per-(s,h): RMS-norm q,k, RoPE q,k, scatter q,k,v into [h][s][d]. (unchanged)
// ---------------------------------------------------------------------------
__global__ void rmsrope_kernel(const float* __restrict__ nq, const float* __restrict__ nk,
                               const float* __restrict__ naq, const float* __restrict__ nak,
                               const float* __restrict__ cosT, const float* __restrict__ sinT)
{
    const int s = blockIdx.x;
    const int h = blockIdx.y;
    const int d = threadIdx.x;

    const float* row = g_QKV + (size_t)s * E3;
    float q = row[h * HD + d];
    float k = row[DM + h * HD + d];
    float v = row[2 * DM + h * HD + d];

    float qq = q * q, kk = k * k;
#pragma unroll
    for (int off = 16; off; off >>= 1) {
        qq += __shfl_xor_sync(0xffffffffu, qq, off);
        kk += __shfl_xor_sync(0xffffffffu, kk, off);
    }
    __shared__ float wq[4], wk[4];
    const int wid = d >> 5, lane = d & 31;
    if (lane == 0) { wq[wid] = qq; wk[wid] = kk; }
    __syncthreads();
    const float sq = wq[0] + wq[1] + wq[2] + wq[3];
    const float sk = wk[0] + wk[1] + wk[2] + wk[3];
    const float rq = rsqrtf(sq * (1.f / 128.f) + 1e-6f);
    const float rk = rsqrtf(sk * (1.f / 128.f) + 1e-6f);

    const bool txt = (s < ST);
    const float qw = txt ? naq[d] : nq[d];
    const float kw = txt ? nak[d] : nk[d];

    __shared__ float qb[128], kb[128];
    qb[d] = q * rq * qw;
    kb[d] = k * rk * kw;

    const size_t base = ((size_t)h * SS + s) * HD;
    g_V[base + d] = v;
    __syncthreads();

    if (d < 64) {
        const float c = cosT[s * 64 + d];
        const float sn = sinT[s * 64 + d];
        float q1 = qb[2 * d], q2 = qb[2 * d + 1];
        g_Q[base + 2 * d]     = q1 * c - q2 * sn;
        g_Q[base + 2 * d + 1] = q2 * c + q1 * sn;
        float k1 = kb[2 * d], k2 = kb[2 * d + 1];
        g_K[base + 2 * d]     = k1 * c - k2 * sn;
        g_K[base + 2 * d + 1] = k2 * c + k1 * sn;
    }
}

// ---------------------------------------------------------------------------
// Flash attention v2: warp-private softmax, register P, cp.async K/V.
// 8 warps; warp w owns q rows [w*16, w*16+16) x all 64 kv of the tile.
// Smem floats: Qs[128][132] tf32, Ks 2x[64][132] raw f32, Vs 2x[64][136] raw.
// ---------------------------------------------------------------------------
#define PADQ 132
#define PADK 132
#define PADV 136
#define A_OFF_KS 16896
#define A_OFF_VS 33792
#define KS_STRIDE 8448               // 64*132
#define VS_STRIDE 8704               // 64*136
#define ATTN_SMEM (51200 * 4)        // 204800 B

__global__ void __launch_bounds__(256, 1) attn_v2()
{
    extern __shared__ float sm[];
    float* Qs = sm;
    const uint32_t smb = smem_u32(sm);

    const int tid  = threadIdx.x;
    const int lane = tid & 31;
    const int w    = tid >> 5;       // warp id 0..7
    const int rl   = lane >> 2;      // 0..7
    const int cq   = lane & 3;       // 0..3
    const int h    = blockIdx.y;
    const int q0   = blockIdx.x * 128;

    const float* Qg = g_Q + ((size_t)h * SS + q0) * HD;
    const float* Kg = g_K + (size_t)h * SS * HD;
    const float* Vg = g_V + (size_t)h * SS * HD;

    // Q tile: tf32-rounded once (scores then bit-identical to R4 path)
#pragma unroll
    for (int t = 0; t < 16; t++) {
        int idx = tid + t * 256;
        int r = idx >> 5, c4 = (idx & 31) * 4;
        float4 v = *(const float4*)&Qg[(size_t)r * HD + c4];
        float* p = &Qs[r * PADQ + c4];
        p[0] = to_tf32(v.x); p[1] = to_tf32(v.y);
        p[2] = to_tf32(v.z); p[3] = to_tf32(v.w);
    }

    auto loadKV = [&](int s, int buf) {
        const int kt = s * 64;
#pragma unroll
        for (int t = 0; t < 8; t++) {
            int idx = tid + t * 256;
            int r = idx >> 5, c4 = (idx & 31) * 4;
            CP16(smb + (uint32_t)(A_OFF_KS + buf * KS_STRIDE + r * PADK + c4) * 4,
                 (const char*)(Kg + (size_t)(kt + r) * HD + c4));
            CP16(smb + (uint32_t)(A_OFF_VS + buf * VS_STRIDE + r * PADV + c4) * 4,
                 (const char*)(Vg + (size_t)(kt + r) * HD + c4));
        }
    };

    float m0 = -1e30f, m1 = -1e30f, l0 = 0.f, l1 = 0.f;
    float oacc[16][4];
#pragma unroll
    for (int nt = 0; nt < 16; nt++)
#pragma unroll
        for (int e = 0; e < 4; e++) oacc[nt][e] = 0.f;

    loadKV(0, 0);
    CP_COMMIT();

    const int src1 = (lane & ~3) | (cq >> 1);
    const int src2 = src1 | 2;
    const bool odd = (cq & 1) != 0;

    for (int it = 0; it < SS / 64; it++) {
        __syncthreads();                       // buffer (it+1)&1 free of readers
        if (it + 1 < SS / 64) loadKV(it + 1, (it + 1) & 1);
        CP_COMMIT();
        CP_WAIT1();                            // tile 'it' landed
        __syncthreads();

        const float* Ksb = sm + A_OFF_KS + (it & 1) * KS_STRIDE;
        const float* Vsb = sm + A_OFF_VS + (it & 1) * VS_STRIDE;

        // ---- S = Q K^T : 16 rows x 64 cols per warp ----
        float sc[8][4];
#pragma unroll
        for (int nt = 0; nt < 8; nt++)
#pragma unroll
            for (int e = 0; e < 4; e++) sc[nt][e] = 0.f;

#pragma unroll
        for (int kk = 0; kk < 16; kk++) {
            unsigned aq[4];
            const float* ap = &Qs[(w * 16 + rl) * PADQ + kk * 8 + cq];
            aq[0] = __float_as_uint(ap[0]);
            aq[1] = __float_as_uint(ap[8 * PADQ]);
            aq[2] = __float_as_uint(ap[4]);
            aq[3] = __float_as_uint(ap[8 * PADQ + 4]);
#pragma unroll
            for (int nt = 0; nt < 8; nt++) {
                const float* bp = &Ksb[(nt * 8 + rl) * PADK + kk * 8 + cq];
                unsigned bf[2] = { tf32_bits(bp[0]), tf32_bits(bp[4]) };
                mma_tf32(sc[nt], aq, bf);
            }
        }

        // ---- warp-private online softmax (rows w*16+rl, +8) ----
        float rmax0 = -1e30f, rmax1 = -1e30f;
#pragma unroll
        for (int nt = 0; nt < 8; nt++) {
#pragma unroll
            for (int e = 0; e < 4; e++) sc[nt][e] *= ATTN_SCALE;
            rmax0 = fmaxf(rmax0, fmaxf(sc[nt][0], sc[nt][1]));
            rmax1 = fmaxf(rmax1, fmaxf(sc[nt][2], sc[nt][3]));
        }
        rmax0 = fmaxf(rmax0, __shfl_xor_sync(0xffffffffu, rmax0, 1));
        rmax0 = fmaxf(rmax0, __shfl_xor_sync(0xffffffffu, rmax0, 2));
        rmax1 = fmaxf(rmax1, __shfl_xor_sync(0xffffffffu, rmax1, 1));
        rmax1 = fmaxf(rmax1, __shfl_xor_sync(0xffffffffu, rmax1, 2));

        const float mn0 = fmaxf(m0, rmax0);
        const float mn1 = fmaxf(m1, rmax1);
        const float f0 = __expf(m0 - mn0);
        const float f1 = __expf(m1 - mn1);
        m0 = mn0; m1 = mn1;

        float rs0 = 0.f, rs1 = 0.f;
#pragma unroll
        for (int nt = 0; nt < 8; nt++) {
            float p0 = __expf(sc[nt][0] - mn0);
            float p1 = __expf(sc[nt][1] - mn0);
            float p2 = __expf(sc[nt][2] - mn1);
            float p3 = __expf(sc[nt][3] - mn1);
            rs0 += p0 + p1;
            rs1 += p2 + p3;
            sc[nt][0] = to_tf32(p0);
            sc[nt][1] = to_tf32(p1);
            sc[nt][2] = to_tf32(p2);
            sc[nt][3] = to_tf32(p3);
        }
        rs0 += __shfl_xor_sync(0xffffffffu, rs0, 1);
        rs0 += __shfl_xor_sync(0xffffffffu, rs0, 2);
        rs1 += __shfl_xor_sync(0xffffffffu, rs1, 1);
        rs1 += __shfl_xor_sync(0xffffffffu, rs1, 2);
        l0 = l0 * f0 + rs0;
        l1 = l1 * f1 + rs1;

#pragma unroll
        for (int nt = 0; nt < 16; nt++) {
            oacc[nt][0] *= f0; oacc[nt][1] *= f0;
            oacc[nt][2] *= f1; oacc[nt][3] *= f1;
        }

        // ---- C-frag -> A-frag relayout of P via quad shuffles ----
        unsigned pf[8][4];
#pragma unroll
        for (int g = 0; g < 8; g++) {
            float x0 = __shfl_sync(0xffffffffu, sc[g][0], src1);
            float x1 = __shfl_sync(0xffffffffu, sc[g][1], src1);
            float y0 = __shfl_sync(0xffffffffu, sc[g][2], src1);
            float y1 = __shfl_sync(0xffffffffu, sc[g][3], src1);
            float z0 = __shfl_sync(0xffffffffu, sc[g][0], src2);
            float z1 = __shfl_sync(0xffffffffu, sc[g][1], src2);
            float u0 = __shfl_sync(0xffffffffu, sc[g][2], src2);
            float u1 = __shfl_sync(0xffffffffu, sc[g][3], src2);
            pf[g][0] = __float_as_uint(odd ? x1 : x0);
            pf[g][1] = __float_as_uint(odd ? y1 : y0);
            pf[g][2] = __float_as_uint(odd ? z1 : z0);
            pf[g][3] = __float_as_uint(odd ? u1 : u0);
        }

        // ---- O += P V : 16 rows x 128 d per warp ----
#pragma unroll
        for (int g = 0; g < 8; g++) {
#pragma unroll
            for (int nt = 0; nt < 16; nt++) {
                const float* vp = &Vsb[(g * 8 + cq) * PADV + nt * 8 + rl];
                unsigned bf[2] = { tf32_bits(vp[0]), tf32_bits(vp[4 * PADV]) };
                mma_tf32(oacc[nt], pf[g], bf);
            }
        }
    }

    // ---- epilogue ----
    const float il0 = 1.f / l0, il1 = 1.f / l1;
    const int r0 = q0 + w * 16 + rl;
    const int r1 = r0 + 8;
#pragma unroll
    for (int nt = 0; nt < 16; nt++) {
        const int col = h * HD + nt * 8 + 2 * cq;
        float2 o;
        o.x = oacc[nt][0] * il0;
        o.y = oacc[nt][1] * il0;
        *(float2*)&g_O[(size_t)r0 * DM + col] = o;
        o.x = oacc[nt][2] * il1;
        o.y = oacc[nt][3] * il1;
        *(float2*)&g_O[(size_t)r1 * DM + col] = o;
    }
}

// ---------------------------------------------------------------------------
extern "C" void kernel_launch(void* const* d_in, const int* in_sizes, int n_in,
                              void* d_out, int out_size)
{
    (void)in_sizes; (void)n_in; (void)out_size;
    const float* hidden = (const float*)d_in[0];
    const float* enc    = (const float*)d_in[1];
    const float* cosT   = (const float*)d_in[2];
    const float* sinT   = (const float*)d_in[3];
    const float* w_qkv  = (const float*)d_in[4];
    const float* b_qkv  = (const float*)d_in[5];
    const float* w_add  = (const float*)d_in[6];
    const float* b_add  = (const float*)d_in[7];
    const float* nq_w   = (const float*)d_in[8];
    const float* nk_w   = (const float*)d_in[9];
    const float* naq_w  = (const float*)d_in[10];
    const float* nak_w  = (const float*)d_in[11];
    const float* w_out  = (const float*)d_in[12];
    const float* b_out  = (const float*)d_in[13];
    const float* w_ao   = (const float*)d_in[14];
    const float* b_ao   = (const float*)d_in[15];
    float* out = (float*)d_out;

    float *qkv = nullptr, *obuf = nullptr;
    cudaGetSymbolAddress((void**)&qkv, g_QKV);
    cudaGetSymbolAddress((void**)&obuf, g_O);
    cudaFuncSetAttribute(attn_v2, cudaFuncAttributeMaxDynamicSharedMemorySize, ATTN_SMEM);
    cudaFuncSetAttribute(gemm_tf32p, cudaFuncAttributeMaxDynamicSharedMemorySize, GEMM_SMEM);

    // QKV projections (text rows 0..511 use w_add; image rows use w_qkv)
    gemm_tf32p<<<dim3(ST / 128, E3 / 256), 256, GEMM_SMEM>>>(
        enc, w_add, b_add, qkv, DM, E3);
    gemm_tf32p<<<dim3(SI / 128, E3 / 256), 256, GEMM_SMEM>>>(
        hidden, w_qkv, b_qkv, qkv + (size_t)ST * E3, DM, E3);

    // RMS norm + RoPE + scatter to [h][s][d]
    rmsrope_kernel<<<dim3(SS, NH), 128>>>(nq_w, nk_w, naq_w, nak_w, cosT, sinT);

    // attention
    attn_v2<<<dim3(SS / 128, NH), 256, ATTN_SMEM>>>();

    // output projections: img_out first, then txt_out
    gemm_tf32p<<<dim3(SI / 128, DM / 256), 256, GEMM_SMEM>>>(
        obuf + (size_t)ST * DM, w_out, b_out, out, DM, DM);
    gemm_tf32p<<<dim3(ST / 128, DM / 256), 256, GEMM_SMEM>>>(
        obuf, w_ao, b_ao, out + (size_t)SI * DM, DM, DM);
}

// round 17
// speedup vs baseline: 3.2169x; 1.0429x over previous
#include <cuda_runtime.h>
#include <cstdint>

#define ST 512
#define SI 2048
#define SS 2560
#define DM 3072
#define NH 24
#define HD 128
#define E3 9216
// ATTN_SCALE * log2(e), folded into Q at the source
#define QSCALE 0.12751744416804414f

// ---------------- scratch (device globals: no allocations allowed) ----------
__device__ float g_QKV[(size_t)SS * E3];      // [s][9216]
__device__ float g_Q[(size_t)NH * SS * HD];   // [h][s][d]  (tf32, pre-scaled)
__device__ float g_K[(size_t)NH * SS * HD];   // [h][s][d]  (tf32)
__device__ float g_V[(size_t)NH * SS * HD];   // [h][s][d]  (tf32)
__device__ float g_O[(size_t)SS * NH * HD];   // [s][h*128+d]

__device__ __forceinline__ uint32_t smem_u32(const void* p) {
    uint32_t a;
    asm("{ .reg .u64 t; cvta.to.shared.u64 t, %1; cvt.u32.u64 %0, t; }" : "=r"(a) : "l"(p));
    return a;
}
__device__ __forceinline__ float to_tf32(float x) {
    float r;
    asm("cvt.rna.tf32.f32 %0, %1;" : "=f"(r) : "f"(x));
    return r;
}
__device__ __forceinline__ unsigned tf32_bits(float x) {
    return __float_as_uint(to_tf32(x));
}
__device__ __forceinline__ void mma_tf32(float (&c)[4], const unsigned (&a)[4],
                                         const unsigned (&b)[2]) {
    asm volatile(
        "mma.sync.aligned.m16n8k8.row.col.f32.tf32.tf32.f32 "
        "{%0,%1,%2,%3}, {%4,%5,%6,%7}, {%8,%9}, {%0,%1,%2,%3};\n"
        : "+f"(c[0]), "+f"(c[1]), "+f"(c[2]), "+f"(c[3])
        : "r"(a[0]), "r"(a[1]), "r"(a[2]), "r"(a[3]), "r"(b[0]), "r"(b[1]));
}
#define CP16(dst, src) \
    asm volatile("cp.async.cg.shared.global [%0], [%1], 16;" :: "r"(dst), "l"(src))
#define CP_COMMIT() asm volatile("cp.async.commit_group;" ::: "memory")
#define CP_WAIT2()  asm volatile("cp.async.wait_group 2;" ::: "memory")
#define CP_WAIT1()  asm volatile("cp.async.wait_group 1;" ::: "memory")

// ---------------------------------------------------------------------------
// Pipelined tf32 GEMM: C[M,N] = A[M,K] * B[N,K]^T + bias[N]  (unchanged, R8)
// ---------------------------------------------------------------------------
#define STAGE_FLOATS 7680            // (128 + 256) * 20
#define STAGE_BYTES  30720
#define GEMM_SMEM    (4 * STAGE_BYTES)

__global__ void __launch_bounds__(256, 1) gemm_tf32p(
    const float* __restrict__ A, const float* __restrict__ B,
    const float* __restrict__ bias, float* __restrict__ C,
    int K, int N)
{
    extern __shared__ float smf[];
    const uint32_t smb = smem_u32(smf);

    const int tid  = threadIdx.x;
    const int lane = tid & 31;
    const int wid  = tid >> 5;
    const int wm   = wid >> 2;
    const int wn   = wid & 3;
    const int rl   = lane >> 2;
    const int cq   = lane & 3;
    const int rowBase = blockIdx.x * 128;
    const int colBase = blockIdx.y * 256;

    const float* Ag = A + (size_t)rowBase * K;
    const float* Bg = B + (size_t)colBase * K;

    const int nSlab = K >> 4;

    const int lr = tid >> 2;
    const int lk4 = (tid & 3) * 4;
    auto load_stage = [&](int s, uint32_t bufb) {
        const int kt = s * 16;
#pragma unroll
        for (int j = 0; j < 2; j++) {
            const int r = lr + j * 64;
            CP16(bufb + (uint32_t)(r * 80 + lk4 * 4),
                 (const char*)(Ag + (size_t)r * K + kt + lk4));
        }
        const uint32_t bb = bufb + 10240u;
#pragma unroll
        for (int j = 0; j < 4; j++) {
            const int r = lr + j * 64;
            CP16(bb + (uint32_t)(r * 80 + lk4 * 4),
                 (const char*)(Bg + (size_t)r * K + kt + lk4));
        }
    };

    float acc[4][8][4];
#pragma unroll
    for (int mt = 0; mt < 4; mt++)
#pragma unroll
        for (int nt = 0; nt < 8; nt++)
#pragma unroll
            for (int e = 0; e < 4; e++) acc[mt][nt][e] = 0.f;

    load_stage(0, smb);                   CP_COMMIT();
    load_stage(1, smb + STAGE_BYTES);     CP_COMMIT();
    load_stage(2, smb + 2 * STAGE_BYTES); CP_COMMIT();

    for (int s = 0; s < nSlab; s++) {
        CP_WAIT2();
        __syncthreads();
        if (s + 3 < nSlab)
            load_stage(s + 3, smb + (uint32_t)((s + 3) & 3) * STAGE_BYTES);
        CP_COMMIT();

        const float* As = smf + (s & 3) * STAGE_FLOATS;
        const float* Bs = As + 2560;
#pragma unroll
        for (int kk = 0; kk < 16; kk += 8) {
            unsigned af[4][4];
#pragma unroll
            for (int mt = 0; mt < 4; mt++) {
                const float* ap = &As[(wm * 64 + mt * 16 + rl) * 20 + kk + cq];
                af[mt][0] = tf32_bits(ap[0]);
                af[mt][1] = tf32_bits(ap[160]);
                af[mt][2] = tf32_bits(ap[4]);
                af[mt][3] = tf32_bits(ap[164]);
            }
            unsigned bf[8][2];
#pragma unroll
            for (int nt = 0; nt < 8; nt++) {
                const float* bp = &Bs[(wn * 64 + nt * 8 + rl) * 20 + kk + cq];
                bf[nt][0] = tf32_bits(bp[0]);
                bf[nt][1] = tf32_bits(bp[4]);
            }
#pragma unroll
            for (int mt = 0; mt < 4; mt++)
#pragma unroll
                for (int nt = 0; nt < 8; nt++)
                    mma_tf32(acc[mt][nt], af[mt], bf[nt]);
        }
    }

#pragma unroll
    for (int mt = 0; mt < 4; mt++) {
        const int r0 = rowBase + wm * 64 + mt * 16 + rl;
#pragma unroll
        for (int nt = 0; nt < 8; nt++) {
            const int c0 = colBase + wn * 64 + nt * 8 + cq * 2;
            float2 b2 = *(const float2*)&bias[c0];
            float2 o;
            o.x = acc[mt][nt][0] + b2.x;
            o.y = acc[mt][nt][1] + b2.y;
            *(float2*)&C[(size_t)r0 * N + c0] = o;
            o.x = acc[mt][nt][2] + b2.x;
            o.y = acc[mt][nt][3] + b2.y;
            *(float2*)&C[(size_t)(r0 + 8) * N + c0] = o;
        }
    }
}

// ---------------------------------------------------------------------------
// Per-(s,h): RMS-norm q,k, RoPE q,k, scatter into [h][s][d].
// Q is stored tf32-rounded with QSCALE folded in; K,V stored tf32-rounded.
// ---------------------------------------------------------------------------
__global__ void rmsrope_kernel(const float* __restrict__ nq, const float* __restrict__ nk,
                               const float* __restrict__ naq, const float* __restrict__ nak,
                               const float* __restrict__ cosT, const float* __restrict__ sinT)
{
    const int s = blockIdx.x;
    const int h = blockIdx.y;
    const int d = threadIdx.x;

    const float* row = g_QKV + (size_t)s * E3;
    float q = row[h * HD + d];
    float k = row[DM + h * HD + d];
    float v = row[2 * DM + h * HD + d];

    float qq = q * q, kk = k * k;
#pragma unroll
    for (int off = 16; off; off >>= 1) {
        qq += __shfl_xor_sync(0xffffffffu, qq, off);
        kk += __shfl_xor_sync(0xffffffffu, kk, off);
    }
    __shared__ float wq[4], wk[4];
    const int wid = d >> 5, lane = d & 31;
    if (lane == 0) { wq[wid] = qq; wk[wid] = kk; }
    __syncthreads();
    const float sq = wq[0] + wq[1] + wq[2] + wq[3];
    const float sk = wk[0] + wk[1] + wk[2] + wk[3];
    const float rq = rsqrtf(sq * (1.f / 128.f) + 1e-6f);
    const float rk = rsqrtf(sk * (1.f / 128.f) + 1e-6f);

    const bool txt = (s < ST);
    const float qw = txt ? naq[d] : nq[d];
    const float kw = txt ? nak[d] : nk[d];

    __shared__ float qb[128], kb[128];
    qb[d] = q * rq * qw;
    kb[d] = k * rk * kw;

    const size_t base = ((size_t)h * SS + s) * HD;
    g_V[base + d] = to_tf32(v);
    __syncthreads();

    if (d < 64) {
        const float c = cosT[s * 64 + d];
        const float sn = sinT[s * 64 + d];
        float q1 = qb[2 * d], q2 = qb[2 * d + 1];
        g_Q[base + 2 * d]     = to_tf32((q1 * c - q2 * sn) * QSCALE);
        g_Q[base + 2 * d + 1] = to_tf32((q2 * c + q1 * sn) * QSCALE);
        float k1 = kb[2 * d], k2 = kb[2 * d + 1];
        g_K[base + 2 * d]     = to_tf32(k1 * c - k2 * sn);
        g_K[base + 2 * d + 1] = to_tf32(k2 * c + k1 * sn);
    }
}

// ---------------------------------------------------------------------------
// Flash attention v3: warp-private softmax (base-2), register P, cp.async K/V,
// all operands pre-rounded to tf32 -> zero cvt in the mma loops.
// ---------------------------------------------------------------------------
#define PADQ 132
#define PADK 132
#define PADV 136
#define A_OFF_KS 16896
#define A_OFF_VS 33792
#define KS_STRIDE 8448               // 64*132
#define VS_STRIDE 8704               // 64*136
#define ATTN_SMEM (51200 * 4)        // 204800 B

__global__ void __launch_bounds__(256, 1) attn_v3()
{
    extern __shared__ float sm[];
    float* Qs = sm;
    const uint32_t smb = smem_u32(sm);

    const int tid  = threadIdx.x;
    const int lane = tid & 31;
    const int w    = tid >> 5;       // warp id 0..7
    const int rl   = lane >> 2;      // 0..7
    const int cq   = lane & 3;       // 0..3
    const int h    = blockIdx.y;
    const int q0   = blockIdx.x * 128;

    const float* Qg = g_Q + ((size_t)h * SS + q0) * HD;
    const float* Kg = g_K + (size_t)h * SS * HD;
    const float* Vg = g_V + (size_t)h * SS * HD;

    // Q tile: already tf32+scaled — raw copy
#pragma unroll
    for (int t = 0; t < 16; t++) {
        int idx = tid + t * 256;
        int r = idx >> 5, c4 = (idx & 31) * 4;
        *(float4*)&Qs[r * PADQ + c4] = *(const float4*)&Qg[(size_t)r * HD + c4];
    }

    auto loadKV = [&](int s, int buf) {
        const int kt = s * 64;
#pragma unroll
        for (int t = 0; t < 8; t++) {
            int idx = tid + t * 256;
            int r = idx >> 5, c4 = (idx & 31) * 4;
            CP16(smb + (uint32_t)(A_OFF_KS + buf * KS_STRIDE + r * PADK + c4) * 4,
                 (const char*)(Kg + (size_t)(kt + r) * HD + c4));
            CP16(smb + (uint32_t)(A_OFF_VS + buf * VS_STRIDE + r * PADV + c4) * 4,
                 (const char*)(Vg + (size_t)(kt + r) * HD + c4));
        }
    };

    float m0 = -1e30f, m1 = -1e30f, l0 = 0.f, l1 = 0.f;
    float oacc[16][4];
#pragma unroll
    for (int nt = 0; nt < 16; nt++)
#pragma unroll
        for (int e = 0; e < 4; e++) oacc[nt][e] = 0.f;

    loadKV(0, 0);
    CP_COMMIT();

    const int src1 = (lane & ~3) | (cq >> 1);
    const int src2 = src1 | 2;
    const bool odd = (cq & 1) != 0;

    for (int it = 0; it < SS / 64; it++) {
        __syncthreads();
        if (it + 1 < SS / 64) loadKV(it + 1, (it + 1) & 1);
        CP_COMMIT();
        CP_WAIT1();
        __syncthreads();

        const float* Ksb = sm + A_OFF_KS + (it & 1) * KS_STRIDE;
        const float* Vsb = sm + A_OFF_VS + (it & 1) * VS_STRIDE;

        // ---- S = Q K^T (scores already in log2 domain via QSCALE) ----
        float sc[8][4];
#pragma unroll
        for (int nt = 0; nt < 8; nt++)
#pragma unroll
            for (int e = 0; e < 4; e++) sc[nt][e] = 0.f;

#pragma unroll
        for (int kk = 0; kk < 16; kk++) {
            unsigned aq[4];
            const float* ap = &Qs[(w * 16 + rl) * PADQ + kk * 8 + cq];
            aq[0] = __float_as_uint(ap[0]);
            aq[1] = __float_as_uint(ap[8 * PADQ]);
            aq[2] = __float_as_uint(ap[4]);
            aq[3] = __float_as_uint(ap[8 * PADQ + 4]);
#pragma unroll
            for (int nt = 0; nt < 8; nt++) {
                const float* bp = &Ksb[(nt * 8 + rl) * PADK + kk * 8 + cq];
                unsigned bf[2] = { __float_as_uint(bp[0]), __float_as_uint(bp[4]) };
                mma_tf32(sc[nt], aq, bf);
            }
        }

        // ---- warp-private online softmax, base-2 ----
        float rmax0 = -1e30f, rmax1 = -1e30f;
#pragma unroll
        for (int nt = 0; nt < 8; nt++) {
            rmax0 = fmaxf(rmax0, fmaxf(sc[nt][0], sc[nt][1]));
            rmax1 = fmaxf(rmax1, fmaxf(sc[nt][2], sc[nt][3]));
        }
        rmax0 = fmaxf(rmax0, __shfl_xor_sync(0xffffffffu, rmax0, 1));
        rmax0 = fmaxf(rmax0, __shfl_xor_sync(0xffffffffu, rmax0, 2));
        rmax1 = fmaxf(rmax1, __shfl_xor_sync(0xffffffffu, rmax1, 1));
        rmax1 = fmaxf(rmax1, __shfl_xor_sync(0xffffffffu, rmax1, 2));

        const float mn0 = fmaxf(m0, rmax0);
        const float mn1 = fmaxf(m1, rmax1);
        const float f0 = exp2f(m0 - mn0);
        const float f1 = exp2f(m1 - mn1);
        m0 = mn0; m1 = mn1;

        float rs0 = 0.f, rs1 = 0.f;
#pragma unroll
        for (int nt = 0; nt < 8; nt++) {
            float p0 = exp2f(sc[nt][0] - mn0);
            float p1 = exp2f(sc[nt][1] - mn0);
            float p2 = exp2f(sc[nt][2] - mn1);
            float p3 = exp2f(sc[nt][3] - mn1);
            rs0 += p0 + p1;
            rs1 += p2 + p3;
            sc[nt][0] = to_tf32(p0);
            sc[nt][1] = to_tf32(p1);
            sc[nt][2] = to_tf32(p2);
            sc[nt][3] = to_tf32(p3);
        }
        rs0 += __shfl_xor_sync(0xffffffffu, rs0, 1);
        rs0 += __shfl_xor_sync(0xffffffffu, rs0, 2);
        rs1 += __shfl_xor_sync(0xffffffffu, rs1, 1);
        rs1 += __shfl_xor_sync(0xffffffffu, rs1, 2);
        l0 = l0 * f0 + rs0;
        l1 = l1 * f1 + rs1;

#pragma unroll
        for (int nt = 0; nt < 16; nt++) {
            oacc[nt][0] *= f0; oacc[nt][1] *= f0;
            oacc[nt][2] *= f1; oacc[nt][3] *= f1;
        }

        // ---- C-frag -> A-frag relayout of P via quad shuffles ----
        unsigned pf[8][4];
#pragma unroll
        for (int g = 0; g < 8; g++) {
            float x0 = __shfl_sync(0xffffffffu, sc[g][0], src1);
            float x1 = __shfl_sync(0xffffffffu, sc[g][1], src1);
            float y0 = __shfl_sync(0xffffffffu, sc[g][2], src1);
            float y1 = __shfl_sync(0xffffffffu, sc[g][3], src1);
            float z0 = __shfl_sync(0xffffffffu, sc[g][0], src2);
            float z1 = __shfl_sync(0xffffffffu, sc[g][1], src2);
            float u0 = __shfl_sync(0xffffffffu, sc[g][2], src2);
            float u1 = __shfl_sync(0xffffffffu, sc[g][3], src2);
            pf[g][0] = __float_as_uint(odd ? x1 : x0);
            pf[g][1] = __float_as_uint(odd ? y1 : y0);
            pf[g][2] = __float_as_uint(odd ? z1 : z0);
            pf[g][3] = __float_as_uint(odd ? u1 : u0);
        }

        // ---- O += P V (V already tf32: plain loads) ----
#pragma unroll
        for (int g = 0; g < 8; g++) {
#pragma unroll
            for (int nt = 0; nt < 16; nt++) {
                const float* vp = &Vsb[(g * 8 + cq) * PADV + nt * 8 + rl];
                unsigned bf[2] = { __float_as_uint(vp[0]),
                                   __float_as_uint(vp[4 * PADV]) };
                mma_tf32(oacc[nt], pf[g], bf);
            }
        }
    }

    // ---- epilogue ----
    const float il0 = 1.f / l0, il1 = 1.f / l1;
    const int r0 = q0 + w * 16 + rl;
    const int r1 = r0 + 8;
#pragma unroll
    for (int nt = 0; nt < 16; nt++) {
        const int col = h * HD + nt * 8 + 2 * cq;
        float2 o;
        o.x = oacc[nt][0] * il0;
        o.y = oacc[nt][1] * il0;
        *(float2*)&g_O[(size_t)r0 * DM + col] = o;
        o.x = oacc[nt][2] * il1;
        o.y = oacc[nt][3] * il1;
        *(float2*)&g_O[(size_t)r1 * DM + col] = o;
    }
}

// ---------------------------------------------------------------------------
extern "C" void kernel_launch(void* const* d_in, const int* in_sizes, int n_in,
                              void* d_out, int out_size)
{
    (void)in_sizes; (void)n_in; (void)out_size;
    const float* hidden = (const float*)d_in[0];
    const float* enc    = (const float*)d_in[1];
    const float* cosT   = (const float*)d_in[2];
    const float* sinT   = (const float*)d_in[3];
    const float* w_qkv  = (const float*)d_in[4];
    const float* b_qkv  = (const float*)d_in[5];
    const float* w_add  = (const float*)d_in[6];
    const float* b_add  = (const float*)d_in[7];
    const float* nq_w   = (const float*)d_in[8];
    const float* nk_w   = (const float*)d_in[9];
    const float* naq_w  = (const float*)d_in[10];
    const float* nak_w  = (const float*)d_in[11];
    const float* w_out  = (const float*)d_in[12];
    const float* b_out  = (const float*)d_in[13];
    const float* w_ao   = (const float*)d_in[14];
    const float* b_ao   = (const float*)d_in[15];
    float* out = (float*)d_out;

    float *qkv = nullptr, *obuf = nullptr;
    cudaGetSymbolAddress((void**)&qkv, g_QKV);
    cudaGetSymbolAddress((void**)&obuf, g_O);
    cudaFuncSetAttribute(attn_v3, cudaFuncAttributeMaxDynamicSharedMemorySize, ATTN_SMEM);
    cudaFuncSetAttribute(gemm_tf32p, cudaFuncAttributeMaxDynamicSharedMemorySize, GEMM_SMEM);

    // QKV projections (text rows 0..511 use w_add; image rows use w_qkv)
    gemm_tf32p<<<dim3(ST / 128, E3 / 256), 256, GEMM_SMEM>>>(
        enc, w_add, b_add, qkv, DM, E3);
    gemm_tf32p<<<dim3(SI / 128, E3 / 256), 256, GEMM_SMEM>>>(
        hidden, w_qkv, b_qkv, qkv + (size_t)ST * E3, DM, E3);

    // RMS norm + RoPE + scatter to [h][s][d]
    rmsrope_kernel<<<dim3(SS, NH), 128>>>(nq_w, nk_w, naq_w, nak_w, cosT, sinT);

    // attention
    attn_v3<<<dim3(SS / 128, NH), 256, ATTN_SMEM>>>();

    // output projections: img_out first, then txt_out
    gemm_tf32p<<<dim3(SI / 128, DM / 256), 256, GEMM_SMEM>>>(
        obuf + (size_t)ST * DM, w_out, b_out, out, DM, DM);
    gemm_tf32p<<<dim3(ST / 128, DM / 256), 256, GEMM_SMEM>>>(
        obuf, w_ao, b_ao, out + (size_t)SI * DM, DM, DM);
}